// round 11
// baseline (speedup 1.0000x reference)
#include <cuda_runtime.h>
#include <cuda_fp16.h>
#include <cstdint>
#include <cstddef>

#define B_ROWS 8192
#define D_IN   1024
#define D_EMB  256
#define K_CENT 1024
#define WSUM   4849664

// ---------------- device scratch ----------------
__device__ __align__(16) __half g_xh[(size_t)B_ROWS * D_IN];
__device__ __align__(16) __half g_xl[(size_t)B_ROWS * D_IN];
__device__ __align__(16) __half g_h0h[(size_t)B_ROWS * 2048];
__device__ __align__(16) __half g_h0l[(size_t)B_ROWS * 2048];
__device__ __align__(16) __half g_h1h[(size_t)B_ROWS * 2048];
__device__ __align__(16) __half g_h1l[(size_t)B_ROWS * 2048];
__device__ __align__(16) __half g_eh[(size_t)B_ROWS * D_EMB];
__device__ __align__(16) __half g_el[(size_t)B_ROWS * D_EMB];
__device__ __align__(16) __half g_weh[WSUM];
__device__ __align__(16) __half g_wel[WSUM];
__device__ __align__(16) __half g_wd[WSUM];
__device__ __align__(16) __half g_ch[K_CENT * D_EMB];
__device__ __align__(16) __half g_cl[K_CENT * D_EMB];
__device__ __align__(16) float  g_S[(size_t)B_ROWS * K_CENT];
__device__ float g_c2[K_CENT];

// ---------------- helpers ----------------
__device__ __forceinline__ uint32_t smem_u32(const void* p) {
    uint32_t a;
    asm("{ .reg .u64 t; cvta.to.shared.u64 t, %1; cvt.u32.u64 %0, t; }" : "=r"(a) : "l"(p));
    return a;
}
__device__ __forceinline__ void split_fp16(float v, __half& h, __half& l) {
    h = __float2half_rn(v);
    l = __float2half_rn(v - __half2float(h));
}
__device__ __forceinline__ void mma_fp16(float* d, const uint32_t* a, const uint32_t* b) {
    asm volatile(
        "mma.sync.aligned.m16n8k16.row.col.f32.f16.f16.f32 "
        "{%0,%1,%2,%3}, {%4,%5,%6,%7}, {%8,%9}, {%0,%1,%2,%3};"
        : "+f"(d[0]), "+f"(d[1]), "+f"(d[2]), "+f"(d[3])
        : "r"(a[0]), "r"(a[1]), "r"(a[2]), "r"(a[3]), "r"(b[0]), "r"(b[1]));
}
#define LDSM_X4(r0, r1, r2, r3, addr) \
    asm volatile("ldmatrix.sync.aligned.m8n8.x4.shared.b16 {%0,%1,%2,%3}, [%4];" \
                 : "=r"(r0), "=r"(r1), "=r"(r2), "=r"(r3) : "r"(addr))
#define CP16(smaddr, gptr) \
    asm volatile("cp.async.cg.shared.global [%0], [%1], 16;" :: "r"(smaddr), "l"(gptr) : "memory")
#define CP_COMMIT() asm volatile("cp.async.commit_group;" ::: "memory")
#define CP_WAIT(n)  asm volatile("cp.async.wait_group %0;" :: "n"(n) : "memory")

// ===========================================================================
// Encoder GEMM: fp16x3 (hh+hl+lh), ldmatrix loads, TERM-MAJOR MMA issue,
// Kahan fold per 2 chunks. Tile 128x64, 8 warps (32x32), BK=32, 3 stages,
// 2 CTAs/SM. Stage bytes: Ah 10240 | Al 10240 | Bh 5120 | Bl 5120 = 30720.
// ===========================================================================
#define FP16E_SMEM (3 * 30720)

__global__ void __launch_bounds__(256, 2)
gemm_fp16e(const __half* __restrict__ Ah, const __half* __restrict__ Al,
           const __half* __restrict__ Bh, const __half* __restrict__ Bl,
           const float* __restrict__ bias,
           float* __restrict__ outF, __half* __restrict__ outH, __half* __restrict__ outL,
           int M, int N, int K, int doRelu)
{
    extern __shared__ __half smh[];
    const int tid  = threadIdx.x;
    const int lane = tid & 31, wid = tid >> 5;
    const int g = lane >> 2, q = lane & 3;
    const int warpM = (wid & 3) * 32, warpN = (wid >> 2) * 32;
    const int brow = blockIdx.y * 128, bcol = blockIdx.x * 64;
    const int nch = K >> 5;
    const uint32_t smb = smem_u32(smh);
    const uint32_t laneOff = (uint32_t)((lane & 15) * 80 + (lane >> 4) * 16);

    float sum[2][4][4], comp[2][4][4], acc[2][4][4];
    #pragma unroll
    for (int i = 0; i < 2; i++)
        #pragma unroll
        for (int j = 0; j < 4; j++)
            #pragma unroll
            for (int r = 0; r < 4; r++) { sum[i][j][r] = 0.f; comp[i][j][r] = 0.f; acc[i][j][r] = 0.f; }

    const __half* gpA[2] = {Ah, Al};
    const __half* gpB[2] = {Bh, Bl};

    auto issue = [&](int ch, int s) {
        int kt = ch << 5;
        uint32_t sbase = smb + (uint32_t)s * 30720u;
        #pragma unroll
        for (int a = 0; a < 2; a++) {
            uint32_t base = sbase + (uint32_t)a * 10240u;
            #pragma unroll
            for (int it = 0; it < 2; it++) {
                int id = it * 256 + tid;
                int row = id >> 2, seg = id & 3;
                CP16(base + (uint32_t)(row * 80 + seg * 16),
                     gpA[a] + (size_t)(brow + row) * K + kt + seg * 8);
            }
        }
        #pragma unroll
        for (int a = 0; a < 2; a++) {
            uint32_t base = sbase + 20480u + (uint32_t)a * 5120u;
            int row = tid >> 2, seg = tid & 3;
            CP16(base + (uint32_t)(row * 80 + seg * 16),
                 gpB[a] + (size_t)(bcol + row) * K + kt + seg * 8);
        }
        CP_COMMIT();
    };

    issue(0, 0);
    if (nch > 1) issue(1, 1); else CP_COMMIT();
    if (nch > 2) issue(2, 2); else CP_COMMIT();

    for (int c = 0; c < nch; c++) {
        int s = c % 3;
        CP_WAIT(2);
        __syncthreads();

        uint32_t sbase = smb + (uint32_t)s * 30720u;
        uint32_t aAh = sbase + (uint32_t)(warpM * 80) + laneOff;
        uint32_t aAl = aAh + 10240u;
        uint32_t aBh = sbase + 20480u + (uint32_t)(warpN * 80) + laneOff;
        uint32_t aBl = aBh + 5120u;

        #pragma unroll
        for (int kb = 0; kb < 2; kb++) {
            uint32_t ko = (uint32_t)(kb * 32);
            uint32_t ah[2][4], al[2][4];
            #pragma unroll
            for (int i = 0; i < 2; i++) {
                LDSM_X4(ah[i][0], ah[i][1], ah[i][2], ah[i][3], aAh + ko + (uint32_t)(i * 16 * 80));
                LDSM_X4(al[i][0], al[i][1], al[i][2], al[i][3], aAl + ko + (uint32_t)(i * 16 * 80));
            }
            #pragma unroll
            for (int p = 0; p < 2; p++) {
                uint32_t bh4[4], bl4[4];
                LDSM_X4(bh4[0], bh4[1], bh4[2], bh4[3], aBh + ko + (uint32_t)(p * 16 * 80));
                LDSM_X4(bl4[0], bl4[1], bl4[2], bl4[3], aBl + ko + (uint32_t)(p * 16 * 80));
                uint32_t bfh0[2] = {bh4[0], bh4[2]}, bfh1[2] = {bh4[1], bh4[3]};
                uint32_t bfl0[2] = {bl4[0], bl4[2]}, bfl1[2] = {bl4[1], bl4[3]};
                // TERM-MAJOR: pass 1 = hh over 4 independent accumulators,
                // then hl, then lh — spaces dependent MMAs by >=4 issues.
                #pragma unroll
                for (int i = 0; i < 2; i++) {
                    mma_fp16(acc[i][p * 2 + 0], ah[i], bfh0);
                    mma_fp16(acc[i][p * 2 + 1], ah[i], bfh1);
                }
                #pragma unroll
                for (int i = 0; i < 2; i++) {
                    mma_fp16(acc[i][p * 2 + 0], ah[i], bfl0);
                    mma_fp16(acc[i][p * 2 + 1], ah[i], bfl1);
                }
                #pragma unroll
                for (int i = 0; i < 2; i++) {
                    mma_fp16(acc[i][p * 2 + 0], al[i], bfh0);
                    mma_fp16(acc[i][p * 2 + 1], al[i], bfh1);
                }
            }
        }

        if ((c & 1) || c == nch - 1) {
            #pragma unroll
            for (int i = 0; i < 2; i++)
                #pragma unroll
                for (int j = 0; j < 4; j++)
                    #pragma unroll
                    for (int r = 0; r < 4; r++) {
                        float v = acc[i][j][r];
                        float so = sum[i][j][r];
                        float t = so + v;
                        comp[i][j][r] += (so - t) + v;
                        sum[i][j][r] = t;
                        acc[i][j][r] = 0.f;
                    }
        }

        __syncthreads();
        if (c + 3 < nch) issue(c + 3, s); else CP_COMMIT();
    }

    #pragma unroll
    for (int i = 0; i < 2; i++) {
        int r0 = brow + warpM + i * 16 + g;
        #pragma unroll
        for (int j = 0; j < 4; j++) {
            int col = bcol + warpN + j * 8 + 2 * q;
            float b0 = 0.f, b1 = 0.f;
            if (bias) { b0 = __ldg(bias + col); b1 = __ldg(bias + col + 1); }
            float v00 = (sum[i][j][0] + comp[i][j][0]) + b0;
            float v01 = (sum[i][j][1] + comp[i][j][1]) + b1;
            float v10 = (sum[i][j][2] + comp[i][j][2]) + b0;
            float v11 = (sum[i][j][3] + comp[i][j][3]) + b1;
            if (doRelu) {
                v00 = fmaxf(v00, 0.f); v01 = fmaxf(v01, 0.f);
                v10 = fmaxf(v10, 0.f); v11 = fmaxf(v11, 0.f);
            }
            size_t o0 = (size_t)r0 * N + col, o1 = o0 + 8 * (size_t)N;
            if (outF) {
                *reinterpret_cast<float2*>(outF + o0) = make_float2(v00, v01);
                *reinterpret_cast<float2*>(outF + o1) = make_float2(v10, v11);
            }
            if (outH) {
                __half h[4], l[4];
                split_fp16(v00, h[0], l[0]); split_fp16(v01, h[1], l[1]);
                split_fp16(v10, h[2], l[2]); split_fp16(v11, h[3], l[3]);
                *reinterpret_cast<__half2*>(outH + o0) = __halves2half2(h[0], h[1]);
                *reinterpret_cast<__half2*>(outH + o1) = __halves2half2(h[2], h[3]);
                *reinterpret_cast<__half2*>(outL + o0) = __halves2half2(l[0], l[1]);
                *reinterpret_cast<__half2*>(outL + o1) = __halves2half2(l[2], l[3]);
            }
        }
    }
}

// ===========================================================================
// Decoder GEMM: fp16x2 asymmetric, ldmatrix loads, term-major issue.
// Stage bytes: Ah 10240 | Al 10240 | W 5120 = 25600.
// ===========================================================================
#define FP16D_SMEM (3 * 25600)

__global__ void __launch_bounds__(256, 2)
gemm_fp16d(const __half* __restrict__ Ah, const __half* __restrict__ Al,
           const __half* __restrict__ W,
           const float* __restrict__ bias,
           float* __restrict__ outF, __half* __restrict__ outH, __half* __restrict__ outL,
           int M, int N, int K, int doRelu)
{
    extern __shared__ __half smh[];
    const int tid  = threadIdx.x;
    const int lane = tid & 31, wid = tid >> 5;
    const int g = lane >> 2, q = lane & 3;
    const int warpM = (wid & 3) * 32, warpN = (wid >> 2) * 32;
    const int brow = blockIdx.y * 128, bcol = blockIdx.x * 64;
    const int nch = K >> 5;
    const uint32_t smb = smem_u32(smh);
    const uint32_t laneOff = (uint32_t)((lane & 15) * 80 + (lane >> 4) * 16);

    float acc[2][4][4];
    #pragma unroll
    for (int i = 0; i < 2; i++)
        #pragma unroll
        for (int j = 0; j < 4; j++)
            #pragma unroll
            for (int r = 0; r < 4; r++) acc[i][j][r] = 0.f;

    const __half* gpA[2] = {Ah, Al};

    auto issue = [&](int ch, int s) {
        int kt = ch << 5;
        uint32_t sbase = smb + (uint32_t)s * 25600u;
        #pragma unroll
        for (int a = 0; a < 2; a++) {
            uint32_t base = sbase + (uint32_t)a * 10240u;
            #pragma unroll
            for (int it = 0; it < 2; it++) {
                int id = it * 256 + tid;
                int row = id >> 2, seg = id & 3;
                CP16(base + (uint32_t)(row * 80 + seg * 16),
                     gpA[a] + (size_t)(brow + row) * K + kt + seg * 8);
            }
        }
        {
            uint32_t base = sbase + 20480u;
            int row = tid >> 2, seg = tid & 3;
            CP16(base + (uint32_t)(row * 80 + seg * 16),
                 W + (size_t)(bcol + row) * K + kt + seg * 8);
        }
        CP_COMMIT();
    };

    issue(0, 0);
    if (nch > 1) issue(1, 1); else CP_COMMIT();
    if (nch > 2) issue(2, 2); else CP_COMMIT();

    for (int c = 0; c < nch; c++) {
        int s = c % 3;
        CP_WAIT(2);
        __syncthreads();

        uint32_t sbase = smb + (uint32_t)s * 25600u;
        uint32_t aAh = sbase + (uint32_t)(warpM * 80) + laneOff;
        uint32_t aAl = aAh + 10240u;
        uint32_t aW  = sbase + 20480u + (uint32_t)(warpN * 80) + laneOff;

        #pragma unroll
        for (int kb = 0; kb < 2; kb++) {
            uint32_t ko = (uint32_t)(kb * 32);
            uint32_t ah[2][4], al[2][4];
            #pragma unroll
            for (int i = 0; i < 2; i++) {
                LDSM_X4(ah[i][0], ah[i][1], ah[i][2], ah[i][3], aAh + ko + (uint32_t)(i * 16 * 80));
                LDSM_X4(al[i][0], al[i][1], al[i][2], al[i][3], aAl + ko + (uint32_t)(i * 16 * 80));
            }
            #pragma unroll
            for (int p = 0; p < 2; p++) {
                uint32_t bw4[4];
                LDSM_X4(bw4[0], bw4[1], bw4[2], bw4[3], aW + ko + (uint32_t)(p * 16 * 80));
                uint32_t bf0[2] = {bw4[0], bw4[2]}, bf1[2] = {bw4[1], bw4[3]};
                #pragma unroll
                for (int i = 0; i < 2; i++) {
                    mma_fp16(acc[i][p * 2 + 0], ah[i], bf0);
                    mma_fp16(acc[i][p * 2 + 1], ah[i], bf1);
                }
                #pragma unroll
                for (int i = 0; i < 2; i++) {
                    mma_fp16(acc[i][p * 2 + 0], al[i], bf0);
                    mma_fp16(acc[i][p * 2 + 1], al[i], bf1);
                }
            }
        }
        __syncthreads();
        if (c + 3 < nch) issue(c + 3, s); else CP_COMMIT();
    }

    #pragma unroll
    for (int i = 0; i < 2; i++) {
        int r0 = brow + warpM + i * 16 + g;
        #pragma unroll
        for (int j = 0; j < 4; j++) {
            int col = bcol + warpN + j * 8 + 2 * q;
            float b0 = 0.f, b1 = 0.f;
            if (bias) { b0 = __ldg(bias + col); b1 = __ldg(bias + col + 1); }
            float v00 = acc[i][j][0] + b0, v01 = acc[i][j][1] + b1;
            float v10 = acc[i][j][2] + b0, v11 = acc[i][j][3] + b1;
            if (doRelu) {
                v00 = fmaxf(v00, 0.f); v01 = fmaxf(v01, 0.f);
                v10 = fmaxf(v10, 0.f); v11 = fmaxf(v11, 0.f);
            }
            size_t o0 = (size_t)r0 * N + col, o1 = o0 + 8 * (size_t)N;
            if (outF) {
                *reinterpret_cast<float2*>(outF + o0) = make_float2(v00, v01);
                *reinterpret_cast<float2*>(outF + o1) = make_float2(v10, v11);
            }
            if (outH) {
                __half h[4], l[4];
                split_fp16(v00, h[0], l[0]); split_fp16(v01, h[1], l[1]);
                split_fp16(v10, h[2], l[2]); split_fp16(v11, h[3], l[3]);
                *reinterpret_cast<__half2*>(outH + o0) = __halves2half2(h[0], h[1]);
                *reinterpret_cast<__half2*>(outH + o1) = __halves2half2(h[2], h[3]);
                *reinterpret_cast<__half2*>(outL + o0) = __halves2half2(l[0], l[1]);
                *reinterpret_cast<__half2*>(outL + o1) = __halves2half2(l[2], l[3]);
            }
        }
    }
}

// ---------------- prep kernels ----------------
__global__ void vec_split_fp16(const float* __restrict__ a,
                               __half* __restrict__ hi, __half* __restrict__ lo, int n2)
{
    int i = blockIdx.x * blockDim.x + threadIdx.x;
    if (i >= n2) return;
    float2 v = reinterpret_cast<const float2*>(a)[i];
    __half hx, lx, hy, ly;
    split_fp16(v.x, hx, lx); split_fp16(v.y, hy, ly);
    reinterpret_cast<__half2*>(hi)[i] = __halves2half2(hx, hy);
    reinterpret_cast<__half2*>(lo)[i] = __halves2half2(lx, ly);
}

__global__ void wt_split_fp16(const float* __restrict__ W, __half* __restrict__ hi,
                              __half* __restrict__ lo, int Kd, int N)
{
    __shared__ float t[32][33];
    int bx = blockIdx.x * 32, by = blockIdx.y * 32;
    for (int i = threadIdx.y; i < 32; i += 8)
        t[i][threadIdx.x] = W[(size_t)(by + i) * N + bx + threadIdx.x];
    __syncthreads();
    for (int i = threadIdx.y; i < 32; i += 8) {
        float v = t[threadIdx.x][i];
        __half h, l;
        split_fp16(v, h, l);
        size_t o = (size_t)(bx + i) * Kd + by + threadIdx.x;
        hi[o] = h; lo[o] = l;
    }
}

__global__ void wt_single_fp16(const float* __restrict__ W, __half* __restrict__ out,
                               int Kd, int N)
{
    __shared__ float t[32][33];
    int bx = blockIdx.x * 32, by = blockIdx.y * 32;
    for (int i = threadIdx.y; i < 32; i += 8)
        t[i][threadIdx.x] = W[(size_t)(by + i) * N + bx + threadIdx.x];
    __syncthreads();
    for (int i = threadIdx.y; i < 32; i += 8)
        out[(size_t)(bx + i) * Kd + by + threadIdx.x] = __float2half_rn(t[threadIdx.x][i]);
}

__global__ void c2_kernel(const float* __restrict__ c, float* __restrict__ c2)
{
    int k = blockIdx.x * 8 + (threadIdx.x >> 5);
    int lane = threadIdx.x & 31;
    float s = 0.0f;
    for (int d = lane; d < D_EMB; d += 32) {
        float v = c[(size_t)k * D_EMB + d];
        s = fmaf(v, v, s);
    }
    #pragma unroll
    for (int o = 16; o; o >>= 1) s += __shfl_xor_sync(0xFFFFFFFFu, s, o);
    if (lane == 0) c2[k] = s;
}

__global__ void argmin_labels(const float* __restrict__ emb, const float* __restrict__ S,
                              const float* __restrict__ c2, float* __restrict__ labels)
{
    const int row = blockIdx.x, tid = threadIdx.x;
    __shared__ float red[256];
    float v = emb[(size_t)row * D_EMB + tid];
    red[tid] = v * v;
    __syncthreads();
    #pragma unroll
    for (int s = 128; s > 0; s >>= 1) {
        if (tid < s) red[tid] += red[tid + s];
        __syncthreads();
    }
    const float e2 = red[0];
    __syncthreads();
    float best = 3.402823466e38f;
    int bi = 0;
    for (int k = tid; k < K_CENT; k += 256) {
        float d = fmaxf(e2 + c2[k] - 2.0f * S[(size_t)row * K_CENT + k], 0.0f);
        if (d < best) { best = d; bi = k; }
    }
    __shared__ float sv[256];
    __shared__ int si[256];
    sv[tid] = best; si[tid] = bi;
    __syncthreads();
    #pragma unroll
    for (int s = 128; s > 0; s >>= 1) {
        if (tid < s) {
            float v2 = sv[tid + s]; int i2 = si[tid + s];
            if (v2 < sv[tid] || (v2 == sv[tid] && i2 < si[tid])) { sv[tid] = v2; si[tid] = i2; }
        }
        __syncthreads();
    }
    const int win = si[0];
    for (int k = tid; k < K_CENT; k += 256)
        labels[(size_t)row * K_CENT + k] = (k == win) ? 1.0f : 0.0f;
}

// ---------------- host launcher ----------------
extern "C" void kernel_launch(void* const* d_in, const int* in_sizes, int n_in,
                              void* d_out, int out_size)
{
    (void)in_sizes; (void)n_in; (void)out_size;

    cudaFuncSetAttribute(gemm_fp16e, cudaFuncAttributeMaxDynamicSharedMemorySize, FP16E_SMEM);
    cudaFuncSetAttribute(gemm_fp16d, cudaFuncAttributeMaxDynamicSharedMemorySize, FP16D_SMEM);

    const float* x = (const float*)d_in[0];
    const float* W[8]  = {(const float*)d_in[1],  (const float*)d_in[3],
                          (const float*)d_in[5],  (const float*)d_in[7],
                          (const float*)d_in[9],  (const float*)d_in[11],
                          (const float*)d_in[13], (const float*)d_in[15]};
    const float* bv[8] = {(const float*)d_in[2],  (const float*)d_in[4],
                          (const float*)d_in[6],  (const float*)d_in[8],
                          (const float*)d_in[10], (const float*)d_in[12],
                          (const float*)d_in[14], (const float*)d_in[16]};
    const float* centers = (const float*)d_in[17];

    float* out    = (float*)d_out;
    float* recon  = out;
    float* emb    = out + (size_t)B_ROWS * D_IN;
    float* labels = emb + (size_t)B_ROWS * D_EMB;

    __half *xh, *xl, *h0h, *h0l, *h1h, *h1l, *eh, *el, *weh, *wel, *wd, *ch, *cl;
    float *S, *c2;
    cudaGetSymbolAddress((void**)&xh, g_xh);   cudaGetSymbolAddress((void**)&xl, g_xl);
    cudaGetSymbolAddress((void**)&h0h, g_h0h); cudaGetSymbolAddress((void**)&h0l, g_h0l);
    cudaGetSymbolAddress((void**)&h1h, g_h1h); cudaGetSymbolAddress((void**)&h1l, g_h1l);
    cudaGetSymbolAddress((void**)&eh, g_eh);   cudaGetSymbolAddress((void**)&el, g_el);
    cudaGetSymbolAddress((void**)&weh, g_weh); cudaGetSymbolAddress((void**)&wel, g_wel);
    cudaGetSymbolAddress((void**)&wd, g_wd);
    cudaGetSymbolAddress((void**)&ch, g_ch);   cudaGetSymbolAddress((void**)&cl, g_cl);
    cudaGetSymbolAddress((void**)&S, g_S);     cudaGetSymbolAddress((void**)&c2, g_c2);

    const int fi[8] = {1024, 2048, 1024, 512, 256, 512, 1024, 2048};
    const int fo[8] = {2048, 1024, 512, 256, 512, 1024, 2048, 1024};
    size_t off[8], acc = 0, accd = 0;
    for (int i = 0; i < 4; i++) { off[i] = acc;  acc  += (size_t)fi[i] * fo[i]; }
    for (int i = 4; i < 8; i++) { off[i] = accd; accd += (size_t)fi[i] * fo[i]; }

    auto wenc = [&](int i) {
        dim3 g(fo[i] / 32, fi[i] / 32), b(32, 8);
        wt_split_fp16<<<g, b>>>(W[i], weh + off[i], wel + off[i], fi[i], fo[i]);
    };

    c2_kernel<<<K_CENT / 8, 256>>>(centers, c2);                               // 1
    vec_split_fp16<<<(B_ROWS * D_IN / 2 + 255) / 256, 256>>>(x, xh, xl,
                                                             B_ROWS * D_IN / 2); // 2
    wenc(0);                                                                   // 3
    {
        dim3 g0(2048 / 64, B_ROWS / 128);                                      // 4
        gemm_fp16e<<<g0, 256, FP16E_SMEM>>>(xh, xl, weh + off[0], wel + off[0], bv[0],
                                            nullptr, h0h, h0l, B_ROWS, 2048, 1024, 1);
    }
    wenc(1);                                                                   // 5
    {
        dim3 g1(1024 / 64, B_ROWS / 128);                                      // 6
        gemm_fp16e<<<g1, 256, FP16E_SMEM>>>(h0h, h0l, weh + off[1], wel + off[1], bv[1],
                                            nullptr, h1h, h1l, B_ROWS, 1024, 2048, 1);
    }
    wenc(2);
    {
        dim3 g2(512 / 64, B_ROWS / 128);
        gemm_fp16e<<<g2, 256, FP16E_SMEM>>>(h1h, h1l, weh + off[2], wel + off[2], bv[2],
                                            nullptr, h0h, h0l, B_ROWS, 512, 1024, 1);
    }
    wenc(3);
    {
        dim3 g3(256 / 64, B_ROWS / 128);
        gemm_fp16e<<<g3, 256, FP16E_SMEM>>>(h0h, h0l, weh + off[3], wel + off[3], bv[3],
                                            emb, eh, el, B_ROWS, 256, 512, 0);
    }

    vec_split_fp16<<<(K_CENT * D_EMB / 2 + 255) / 256, 256>>>(centers, ch, cl,
                                                              K_CENT * D_EMB / 2);
    {
        dim3 g(K_CENT / 64, B_ROWS / 128);
        gemm_fp16e<<<g, 256, FP16E_SMEM>>>(eh, el, ch, cl, nullptr,
                                           S, nullptr, nullptr, B_ROWS, K_CENT, D_EMB, 0);
    }
    argmin_labels<<<B_ROWS, 256>>>(emb, S, c2, labels);

    for (int i = 4; i < 8; i++) {
        dim3 g(fo[i] / 32, fi[i] / 32), b(32, 8);
        wt_single_fp16<<<g, b>>>(W[i], wd + off[i], fi[i], fo[i]);
    }
    {
        dim3 g0(512 / 64, B_ROWS / 128);
        gemm_fp16d<<<g0, 256, FP16D_SMEM>>>(eh, el, wd + off[4], bv[4],
                                            nullptr, h0h, h0l, B_ROWS, 512, 256, 1);
        dim3 g1(1024 / 64, B_ROWS / 128);
        gemm_fp16d<<<g1, 256, FP16D_SMEM>>>(h0h, h0l, wd + off[5], bv[5],
                                            nullptr, h1h, h1l, B_ROWS, 1024, 512, 1);
        dim3 g2(2048 / 64, B_ROWS / 128);
        gemm_fp16d<<<g2, 256, FP16D_SMEM>>>(h1h, h1l, wd + off[6], bv[6],
                                            nullptr, h0h, h0l, B_ROWS, 2048, 1024, 1);
        dim3 g3(1024 / 64, B_ROWS / 128);
        gemm_fp16d<<<g3, 256, FP16D_SMEM>>>(h0h, h0l, wd + off[7], bv[7],
                                            recon, nullptr, nullptr, B_ROWS, 1024, 2048, 0);
    }
}

// round 12
// speedup vs baseline: 1.3198x; 1.3198x over previous
#include <cuda_runtime.h>
#include <cuda_fp16.h>
#include <cstdint>
#include <cstddef>

#define B_ROWS 8192
#define D_IN   1024
#define D_EMB  256
#define K_CENT 1024
#define WSUM   4849664

// ---------------- device scratch ----------------
__device__ __align__(16) __half g_xh[(size_t)B_ROWS * D_IN];
__device__ __align__(16) __half g_xl[(size_t)B_ROWS * D_IN];
__device__ __align__(16) __half g_h0h[(size_t)B_ROWS * 2048];
__device__ __align__(16) __half g_h0l[(size_t)B_ROWS * 2048];
__device__ __align__(16) __half g_h1h[(size_t)B_ROWS * 2048];
__device__ __align__(16) __half g_h1l[(size_t)B_ROWS * 2048];
__device__ __align__(16) __half g_eh[(size_t)B_ROWS * D_EMB];
__device__ __align__(16) __half g_el[(size_t)B_ROWS * D_EMB];
__device__ __align__(16) __half g_weh[WSUM];
__device__ __align__(16) __half g_wel[WSUM];
__device__ __align__(16) __half g_wd[WSUM];
__device__ __align__(16) __half g_ch[K_CENT * D_EMB];
__device__ __align__(16) __half g_cl[K_CENT * D_EMB];
__device__ __align__(16) float  g_S[(size_t)B_ROWS * K_CENT];
__device__ float g_c2[K_CENT];

// ---------------- helpers ----------------
__device__ __forceinline__ uint32_t smem_u32(const void* p) {
    uint32_t a;
    asm("{ .reg .u64 t; cvta.to.shared.u64 t, %1; cvt.u32.u64 %0, t; }" : "=r"(a) : "l"(p));
    return a;
}
__device__ __forceinline__ void split_fp16(float v, __half& h, __half& l) {
    h = __float2half_rn(v);
    l = __float2half_rn(v - __half2float(h));
}
__device__ __forceinline__ void mma_fp16(float* d, const uint32_t* a, const uint32_t* b) {
    asm volatile(
        "mma.sync.aligned.m16n8k16.row.col.f32.f16.f16.f32 "
        "{%0,%1,%2,%3}, {%4,%5,%6,%7}, {%8,%9}, {%0,%1,%2,%3};"
        : "+f"(d[0]), "+f"(d[1]), "+f"(d[2]), "+f"(d[3])
        : "r"(a[0]), "r"(a[1]), "r"(a[2]), "r"(a[3]), "r"(b[0]), "r"(b[1]));
}
#define LDSM_X4(r0, r1, r2, r3, addr) \
    asm volatile("ldmatrix.sync.aligned.m8n8.x4.shared.b16 {%0,%1,%2,%3}, [%4];" \
                 : "=r"(r0), "=r"(r1), "=r"(r2), "=r"(r3) : "r"(addr))
#define CP16(smaddr, gptr) \
    asm volatile("cp.async.cg.shared.global [%0], [%1], 16;" :: "r"(smaddr), "l"(gptr) : "memory")
#define CP_COMMIT() asm volatile("cp.async.commit_group;" ::: "memory")
#define CP_WAIT(n)  asm volatile("cp.async.wait_group %0;" :: "n"(n) : "memory")

// ===========================================================================
// Encoder GEMM: fp16x3 (hh+hl+lh), ldmatrix loads, plain chunked-sum
// (accumulator zeroed & folded every 2 chunks). Tile 128x64, 8 warps,
// BK=32, 3 stages, 2 CTAs/SM.
// ===========================================================================
#define FP16E_SMEM (3 * 30720)

__global__ void __launch_bounds__(256, 2)
gemm_fp16e(const __half* __restrict__ Ah, const __half* __restrict__ Al,
           const __half* __restrict__ Bh, const __half* __restrict__ Bl,
           const float* __restrict__ bias,
           float* __restrict__ outF, __half* __restrict__ outH, __half* __restrict__ outL,
           int M, int N, int K, int doRelu)
{
    extern __shared__ __half smh[];
    const int tid  = threadIdx.x;
    const int lane = tid & 31, wid = tid >> 5;
    const int g = lane >> 2, q = lane & 3;
    const int warpM = (wid & 3) * 32, warpN = (wid >> 2) * 32;
    const int brow = blockIdx.y * 128, bcol = blockIdx.x * 64;
    const int nch = K >> 5;
    const uint32_t smb = smem_u32(smh);
    const uint32_t laneOff = (uint32_t)((lane & 15) * 80 + (lane >> 4) * 16);

    float sum[2][4][4], acc[2][4][4];
    #pragma unroll
    for (int i = 0; i < 2; i++)
        #pragma unroll
        for (int j = 0; j < 4; j++)
            #pragma unroll
            for (int r = 0; r < 4; r++) { sum[i][j][r] = 0.f; acc[i][j][r] = 0.f; }

    const __half* gpA[2] = {Ah, Al};
    const __half* gpB[2] = {Bh, Bl};

    auto issue = [&](int ch, int s) {
        int kt = ch << 5;
        uint32_t sbase = smb + (uint32_t)s * 30720u;
        #pragma unroll
        for (int a = 0; a < 2; a++) {
            uint32_t base = sbase + (uint32_t)a * 10240u;
            #pragma unroll
            for (int it = 0; it < 2; it++) {
                int id = it * 256 + tid;
                int row = id >> 2, seg = id & 3;
                CP16(base + (uint32_t)(row * 80 + seg * 16),
                     gpA[a] + (size_t)(brow + row) * K + kt + seg * 8);
            }
        }
        #pragma unroll
        for (int a = 0; a < 2; a++) {
            uint32_t base = sbase + 20480u + (uint32_t)a * 5120u;
            int row = tid >> 2, seg = tid & 3;
            CP16(base + (uint32_t)(row * 80 + seg * 16),
                 gpB[a] + (size_t)(bcol + row) * K + kt + seg * 8);
        }
        CP_COMMIT();
    };

    issue(0, 0);
    if (nch > 1) issue(1, 1); else CP_COMMIT();
    if (nch > 2) issue(2, 2); else CP_COMMIT();

    for (int c = 0; c < nch; c++) {
        int s = c % 3;
        CP_WAIT(2);
        __syncthreads();

        uint32_t sbase = smb + (uint32_t)s * 30720u;
        uint32_t aAh = sbase + (uint32_t)(warpM * 80) + laneOff;
        uint32_t aAl = aAh + 10240u;
        uint32_t aBh = sbase + 20480u + (uint32_t)(warpN * 80) + laneOff;
        uint32_t aBl = aBh + 5120u;

        #pragma unroll
        for (int kb = 0; kb < 2; kb++) {
            uint32_t ko = (uint32_t)(kb * 32);
            uint32_t ah[2][4], al[2][4];
            #pragma unroll
            for (int i = 0; i < 2; i++) {
                LDSM_X4(ah[i][0], ah[i][1], ah[i][2], ah[i][3], aAh + ko + (uint32_t)(i * 16 * 80));
                LDSM_X4(al[i][0], al[i][1], al[i][2], al[i][3], aAl + ko + (uint32_t)(i * 16 * 80));
            }
            #pragma unroll
            for (int p = 0; p < 2; p++) {
                uint32_t bh4[4], bl4[4];
                LDSM_X4(bh4[0], bh4[1], bh4[2], bh4[3], aBh + ko + (uint32_t)(p * 16 * 80));
                LDSM_X4(bl4[0], bl4[1], bl4[2], bl4[3], aBl + ko + (uint32_t)(p * 16 * 80));
                uint32_t bfh0[2] = {bh4[0], bh4[2]}, bfh1[2] = {bh4[1], bh4[3]};
                uint32_t bfl0[2] = {bl4[0], bl4[2]}, bfl1[2] = {bl4[1], bl4[3]};
                #pragma unroll
                for (int i = 0; i < 2; i++) {
                    mma_fp16(acc[i][p * 2 + 0], ah[i], bfh0);
                    mma_fp16(acc[i][p * 2 + 1], ah[i], bfh1);
                }
                #pragma unroll
                for (int i = 0; i < 2; i++) {
                    mma_fp16(acc[i][p * 2 + 0], ah[i], bfl0);
                    mma_fp16(acc[i][p * 2 + 1], ah[i], bfl1);
                }
                #pragma unroll
                for (int i = 0; i < 2; i++) {
                    mma_fp16(acc[i][p * 2 + 0], al[i], bfh0);
                    mma_fp16(acc[i][p * 2 + 1], al[i], bfh1);
                }
            }
        }

        if ((c & 1) || c == nch - 1) {
            #pragma unroll
            for (int i = 0; i < 2; i++)
                #pragma unroll
                for (int j = 0; j < 4; j++)
                    #pragma unroll
                    for (int r = 0; r < 4; r++) {
                        sum[i][j][r] += acc[i][j][r];
                        acc[i][j][r] = 0.f;
                    }
        }

        __syncthreads();
        if (c + 3 < nch) issue(c + 3, s); else CP_COMMIT();
    }

    #pragma unroll
    for (int i = 0; i < 2; i++) {
        int r0 = brow + warpM + i * 16 + g;
        #pragma unroll
        for (int j = 0; j < 4; j++) {
            int col = bcol + warpN + j * 8 + 2 * q;
            float b0 = 0.f, b1 = 0.f;
            if (bias) { b0 = __ldg(bias + col); b1 = __ldg(bias + col + 1); }
            float v00 = sum[i][j][0] + b0;
            float v01 = sum[i][j][1] + b1;
            float v10 = sum[i][j][2] + b0;
            float v11 = sum[i][j][3] + b1;
            if (doRelu) {
                v00 = fmaxf(v00, 0.f); v01 = fmaxf(v01, 0.f);
                v10 = fmaxf(v10, 0.f); v11 = fmaxf(v11, 0.f);
            }
            size_t o0 = (size_t)r0 * N + col, o1 = o0 + 8 * (size_t)N;
            if (outF) {
                *reinterpret_cast<float2*>(outF + o0) = make_float2(v00, v01);
                *reinterpret_cast<float2*>(outF + o1) = make_float2(v10, v11);
            }
            if (outH) {
                __half h[4], l[4];
                split_fp16(v00, h[0], l[0]); split_fp16(v01, h[1], l[1]);
                split_fp16(v10, h[2], l[2]); split_fp16(v11, h[3], l[3]);
                *reinterpret_cast<__half2*>(outH + o0) = __halves2half2(h[0], h[1]);
                *reinterpret_cast<__half2*>(outH + o1) = __halves2half2(h[2], h[3]);
                *reinterpret_cast<__half2*>(outL + o0) = __halves2half2(l[0], l[1]);
                *reinterpret_cast<__half2*>(outL + o1) = __halves2half2(l[2], l[3]);
            }
        }
    }
}

// ===========================================================================
// Decoder GEMM: fp16x1 (single-fp16 activations AND weights).
// Tile 128x64, 8 warps (32x32), BK=32, 3 stages, 3 CTAs/SM.
// Stage bytes: A 10240 | W 5120 = 15360.
// ===========================================================================
#define FP16S_SMEM (3 * 15360)

__global__ void __launch_bounds__(256, 3)
gemm_fp16s(const __half* __restrict__ A, const __half* __restrict__ W,
           const float* __restrict__ bias,
           float* __restrict__ outF, __half* __restrict__ outH,
           int M, int N, int K, int doRelu)
{
    extern __shared__ __half smh[];
    const int tid  = threadIdx.x;
    const int lane = tid & 31, wid = tid >> 5;
    const int g = lane >> 2, q = lane & 3;
    const int warpM = (wid & 3) * 32, warpN = (wid >> 2) * 32;
    const int brow = blockIdx.y * 128, bcol = blockIdx.x * 64;
    const int nch = K >> 5;
    const uint32_t smb = smem_u32(smh);
    const uint32_t laneOff = (uint32_t)((lane & 15) * 80 + (lane >> 4) * 16);

    float acc[2][4][4];
    #pragma unroll
    for (int i = 0; i < 2; i++)
        #pragma unroll
        for (int j = 0; j < 4; j++)
            #pragma unroll
            for (int r = 0; r < 4; r++) acc[i][j][r] = 0.f;

    auto issue = [&](int ch, int s) {
        int kt = ch << 5;
        uint32_t sbase = smb + (uint32_t)s * 15360u;
        #pragma unroll
        for (int it = 0; it < 2; it++) {
            int id = it * 256 + tid;
            int row = id >> 2, seg = id & 3;
            CP16(sbase + (uint32_t)(row * 80 + seg * 16),
                 A + (size_t)(brow + row) * K + kt + seg * 8);
        }
        {
            uint32_t base = sbase + 10240u;
            int row = tid >> 2, seg = tid & 3;
            CP16(base + (uint32_t)(row * 80 + seg * 16),
                 W + (size_t)(bcol + row) * K + kt + seg * 8);
        }
        CP_COMMIT();
    };

    issue(0, 0);
    if (nch > 1) issue(1, 1); else CP_COMMIT();
    if (nch > 2) issue(2, 2); else CP_COMMIT();

    for (int c = 0; c < nch; c++) {
        int s = c % 3;
        CP_WAIT(2);
        __syncthreads();

        uint32_t sbase = smb + (uint32_t)s * 15360u;
        uint32_t aA = sbase + (uint32_t)(warpM * 80) + laneOff;
        uint32_t aW = sbase + 10240u + (uint32_t)(warpN * 80) + laneOff;

        #pragma unroll
        for (int kb = 0; kb < 2; kb++) {
            uint32_t ko = (uint32_t)(kb * 32);
            uint32_t a4[2][4];
            #pragma unroll
            for (int i = 0; i < 2; i++)
                LDSM_X4(a4[i][0], a4[i][1], a4[i][2], a4[i][3], aA + ko + (uint32_t)(i * 16 * 80));
            #pragma unroll
            for (int p = 0; p < 2; p++) {
                uint32_t w4[4];
                LDSM_X4(w4[0], w4[1], w4[2], w4[3], aW + ko + (uint32_t)(p * 16 * 80));
                uint32_t bf0[2] = {w4[0], w4[2]}, bf1[2] = {w4[1], w4[3]};
                #pragma unroll
                for (int i = 0; i < 2; i++) {
                    mma_fp16(acc[i][p * 2 + 0], a4[i], bf0);
                    mma_fp16(acc[i][p * 2 + 1], a4[i], bf1);
                }
            }
        }
        __syncthreads();
        if (c + 3 < nch) issue(c + 3, s); else CP_COMMIT();
    }

    #pragma unroll
    for (int i = 0; i < 2; i++) {
        int r0 = brow + warpM + i * 16 + g;
        #pragma unroll
        for (int j = 0; j < 4; j++) {
            int col = bcol + warpN + j * 8 + 2 * q;
            float b0 = 0.f, b1 = 0.f;
            if (bias) { b0 = __ldg(bias + col); b1 = __ldg(bias + col + 1); }
            float v00 = acc[i][j][0] + b0, v01 = acc[i][j][1] + b1;
            float v10 = acc[i][j][2] + b0, v11 = acc[i][j][3] + b1;
            if (doRelu) {
                v00 = fmaxf(v00, 0.f); v01 = fmaxf(v01, 0.f);
                v10 = fmaxf(v10, 0.f); v11 = fmaxf(v11, 0.f);
            }
            size_t o0 = (size_t)r0 * N + col, o1 = o0 + 8 * (size_t)N;
            if (outF) {
                *reinterpret_cast<float2*>(outF + o0) = make_float2(v00, v01);
                *reinterpret_cast<float2*>(outF + o1) = make_float2(v10, v11);
            }
            if (outH) {
                *reinterpret_cast<__half2*>(outH + o0) =
                    __halves2half2(__float2half_rn(v00), __float2half_rn(v01));
                *reinterpret_cast<__half2*>(outH + o1) =
                    __halves2half2(__float2half_rn(v10), __float2half_rn(v11));
            }
        }
    }
}

// ---------------- prep kernels ----------------
__global__ void vec_split_fp16(const float* __restrict__ a,
                               __half* __restrict__ hi, __half* __restrict__ lo, int n2)
{
    int i = blockIdx.x * blockDim.x + threadIdx.x;
    if (i >= n2) return;
    float2 v = reinterpret_cast<const float2*>(a)[i];
    __half hx, lx, hy, ly;
    split_fp16(v.x, hx, lx); split_fp16(v.y, hy, ly);
    reinterpret_cast<__half2*>(hi)[i] = __halves2half2(hx, hy);
    reinterpret_cast<__half2*>(lo)[i] = __halves2half2(lx, ly);
}

__global__ void wt_split_fp16(const float* __restrict__ W, __half* __restrict__ hi,
                              __half* __restrict__ lo, int Kd, int N)
{
    __shared__ float t[32][33];
    int bx = blockIdx.x * 32, by = blockIdx.y * 32;
    for (int i = threadIdx.y; i < 32; i += 8)
        t[i][threadIdx.x] = W[(size_t)(by + i) * N + bx + threadIdx.x];
    __syncthreads();
    for (int i = threadIdx.y; i < 32; i += 8) {
        float v = t[threadIdx.x][i];
        __half h, l;
        split_fp16(v, h, l);
        size_t o = (size_t)(bx + i) * Kd + by + threadIdx.x;
        hi[o] = h; lo[o] = l;
    }
}

__global__ void wt_single_fp16(const float* __restrict__ W, __half* __restrict__ out,
                               int Kd, int N)
{
    __shared__ float t[32][33];
    int bx = blockIdx.x * 32, by = blockIdx.y * 32;
    for (int i = threadIdx.y; i < 32; i += 8)
        t[i][threadIdx.x] = W[(size_t)(by + i) * N + bx + threadIdx.x];
    __syncthreads();
    for (int i = threadIdx.y; i < 32; i += 8)
        out[(size_t)(bx + i) * Kd + by + threadIdx.x] = __float2half_rn(t[threadIdx.x][i]);
}

__global__ void c2_kernel(const float* __restrict__ c, float* __restrict__ c2)
{
    int k = blockIdx.x * 8 + (threadIdx.x >> 5);
    int lane = threadIdx.x & 31;
    float s = 0.0f;
    for (int d = lane; d < D_EMB; d += 32) {
        float v = c[(size_t)k * D_EMB + d];
        s = fmaf(v, v, s);
    }
    #pragma unroll
    for (int o = 16; o; o >>= 1) s += __shfl_xor_sync(0xFFFFFFFFu, s, o);
    if (lane == 0) c2[k] = s;
}

__global__ void argmin_labels(const float* __restrict__ emb, const float* __restrict__ S,
                              const float* __restrict__ c2, float* __restrict__ labels)
{
    const int row = blockIdx.x, tid = threadIdx.x;
    __shared__ float red[256];
    float v = emb[(size_t)row * D_EMB + tid];
    red[tid] = v * v;
    __syncthreads();
    #pragma unroll
    for (int s = 128; s > 0; s >>= 1) {
        if (tid < s) red[tid] += red[tid + s];
        __syncthreads();
    }
    const float e2 = red[0];
    __syncthreads();
    float best = 3.402823466e38f;
    int bi = 0;
    for (int k = tid; k < K_CENT; k += 256) {
        float d = fmaxf(e2 + c2[k] - 2.0f * S[(size_t)row * K_CENT + k], 0.0f);
        if (d < best) { best = d; bi = k; }
    }
    __shared__ float sv[256];
    __shared__ int si[256];
    sv[tid] = best; si[tid] = bi;
    __syncthreads();
    #pragma unroll
    for (int s = 128; s > 0; s >>= 1) {
        if (tid < s) {
            float v2 = sv[tid + s]; int i2 = si[tid + s];
            if (v2 < sv[tid] || (v2 == sv[tid] && i2 < si[tid])) { sv[tid] = v2; si[tid] = i2; }
        }
        __syncthreads();
    }
    const int win = si[0];
    for (int k = tid; k < K_CENT; k += 256)
        labels[(size_t)row * K_CENT + k] = (k == win) ? 1.0f : 0.0f;
}

// ---------------- host launcher ----------------
extern "C" void kernel_launch(void* const* d_in, const int* in_sizes, int n_in,
                              void* d_out, int out_size)
{
    (void)in_sizes; (void)n_in; (void)out_size;

    cudaFuncSetAttribute(gemm_fp16e, cudaFuncAttributeMaxDynamicSharedMemorySize, FP16E_SMEM);
    cudaFuncSetAttribute(gemm_fp16s, cudaFuncAttributeMaxDynamicSharedMemorySize, FP16S_SMEM);

    const float* x = (const float*)d_in[0];
    const float* W[8]  = {(const float*)d_in[1],  (const float*)d_in[3],
                          (const float*)d_in[5],  (const float*)d_in[7],
                          (const float*)d_in[9],  (const float*)d_in[11],
                          (const float*)d_in[13], (const float*)d_in[15]};
    const float* bv[8] = {(const float*)d_in[2],  (const float*)d_in[4],
                          (const float*)d_in[6],  (const float*)d_in[8],
                          (const float*)d_in[10], (const float*)d_in[12],
                          (const float*)d_in[14], (const float*)d_in[16]};
    const float* centers = (const float*)d_in[17];

    float* out    = (float*)d_out;
    float* recon  = out;
    float* emb    = out + (size_t)B_ROWS * D_IN;
    float* labels = emb + (size_t)B_ROWS * D_EMB;

    __half *xh, *xl, *h0h, *h0l, *h1h, *h1l, *eh, *el, *weh, *wel, *wd, *ch, *cl;
    float *S, *c2;
    cudaGetSymbolAddress((void**)&xh, g_xh);   cudaGetSymbolAddress((void**)&xl, g_xl);
    cudaGetSymbolAddress((void**)&h0h, g_h0h); cudaGetSymbolAddress((void**)&h0l, g_h0l);
    cudaGetSymbolAddress((void**)&h1h, g_h1h); cudaGetSymbolAddress((void**)&h1l, g_h1l);
    cudaGetSymbolAddress((void**)&eh, g_eh);   cudaGetSymbolAddress((void**)&el, g_el);
    cudaGetSymbolAddress((void**)&weh, g_weh); cudaGetSymbolAddress((void**)&wel, g_wel);
    cudaGetSymbolAddress((void**)&wd, g_wd);
    cudaGetSymbolAddress((void**)&ch, g_ch);   cudaGetSymbolAddress((void**)&cl, g_cl);
    cudaGetSymbolAddress((void**)&S, g_S);     cudaGetSymbolAddress((void**)&c2, g_c2);

    const int fi[8] = {1024, 2048, 1024, 512, 256, 512, 1024, 2048};
    const int fo[8] = {2048, 1024, 512, 256, 512, 1024, 2048, 1024};
    size_t off[8], acc = 0, accd = 0;
    for (int i = 0; i < 4; i++) { off[i] = acc;  acc  += (size_t)fi[i] * fo[i]; }
    for (int i = 4; i < 8; i++) { off[i] = accd; accd += (size_t)fi[i] * fo[i]; }

    auto wenc = [&](int i) {
        dim3 g(fo[i] / 32, fi[i] / 32), b(32, 8);
        wt_split_fp16<<<g, b>>>(W[i], weh + off[i], wel + off[i], fi[i], fo[i]);
    };

    c2_kernel<<<K_CENT / 8, 256>>>(centers, c2);                               // 1
    vec_split_fp16<<<(B_ROWS * D_IN / 2 + 255) / 256, 256>>>(x, xh, xl,
                                                             B_ROWS * D_IN / 2); // 2
    wenc(0);                                                                   // 3
    {
        dim3 g0(2048 / 64, B_ROWS / 128);                                      // 4
        gemm_fp16e<<<g0, 256, FP16E_SMEM>>>(xh, xl, weh + off[0], wel + off[0], bv[0],
                                            nullptr, h0h, h0l, B_ROWS, 2048, 1024, 1);
    }
    wenc(1);                                                                   // 5
    {
        dim3 g1(1024 / 64, B_ROWS / 128);                                      // 6
        gemm_fp16e<<<g1, 256, FP16E_SMEM>>>(h0h, h0l, weh + off[1], wel + off[1], bv[1],
                                            nullptr, h1h, h1l, B_ROWS, 1024, 2048, 1);
    }
    wenc(2);
    {
        dim3 g2(512 / 64, B_ROWS / 128);
        gemm_fp16e<<<g2, 256, FP16E_SMEM>>>(h1h, h1l, weh + off[2], wel + off[2], bv[2],
                                            nullptr, h0h, h0l, B_ROWS, 512, 1024, 1);
    }
    wenc(3);
    {
        dim3 g3(256 / 64, B_ROWS / 128);
        gemm_fp16e<<<g3, 256, FP16E_SMEM>>>(h0h, h0l, weh + off[3], wel + off[3], bv[3],
                                            emb, eh, el, B_ROWS, 256, 512, 0);
    }

    vec_split_fp16<<<(K_CENT * D_EMB / 2 + 255) / 256, 256>>>(centers, ch, cl,
                                                              K_CENT * D_EMB / 2);
    {
        dim3 g(K_CENT / 64, B_ROWS / 128);
        gemm_fp16e<<<g, 256, FP16E_SMEM>>>(eh, el, ch, cl, nullptr,
                                           S, nullptr, nullptr, B_ROWS, K_CENT, D_EMB, 0);
    }
    argmin_labels<<<B_ROWS, 256>>>(emb, S, c2, labels);

    for (int i = 4; i < 8; i++) {
        dim3 g(fo[i] / 32, fi[i] / 32), b(32, 8);
        wt_single_fp16<<<g, b>>>(W[i], wd + off[i], fi[i], fo[i]);
    }
    // decoder fp16x1: act buffers single-half (reuse h0h/h1h)
    {
        dim3 g0(512 / 64, B_ROWS / 128);
        gemm_fp16s<<<g0, 256, FP16S_SMEM>>>(eh, wd + off[4], bv[4],
                                            nullptr, h0h, B_ROWS, 512, 256, 1);
        dim3 g1(1024 / 64, B_ROWS / 128);
        gemm_fp16s<<<g1, 256, FP16S_SMEM>>>(h0h, wd + off[5], bv[5],
                                            nullptr, h1h, B_ROWS, 1024, 512, 1);
        dim3 g2(2048 / 64, B_ROWS / 128);
        gemm_fp16s<<<g2, 256, FP16S_SMEM>>>(h1h, wd + off[6], bv[6],
                                            nullptr, h0h, B_ROWS, 2048, 1024, 1);
        dim3 g3(1024 / 64, B_ROWS / 128);
        gemm_fp16s<<<g3, 256, FP16S_SMEM>>>(h0h, wd + off[7], bv[7],
                                            recon, nullptr, B_ROWS, 1024, 2048, 0);
    }
}

// round 13
// speedup vs baseline: 1.3558x; 1.0273x over previous
#include <cuda_runtime.h>
#include <cuda_fp16.h>
#include <cstdint>
#include <cstddef>

#define B_ROWS 8192
#define D_IN   1024
#define D_EMB  256
#define K_CENT 1024
#define WSUM   4849664

// ---------------- device scratch ----------------
__device__ __align__(16) __half g_xh[(size_t)B_ROWS * D_IN];
__device__ __align__(16) __half g_xl[(size_t)B_ROWS * D_IN];
__device__ __align__(16) __half g_h0h[(size_t)B_ROWS * 2048];
__device__ __align__(16) __half g_h0l[(size_t)B_ROWS * 2048];
__device__ __align__(16) __half g_h1h[(size_t)B_ROWS * 2048];
__device__ __align__(16) __half g_h1l[(size_t)B_ROWS * 2048];
__device__ __align__(16) __half g_eh[(size_t)B_ROWS * D_EMB];
__device__ __align__(16) __half g_el[(size_t)B_ROWS * D_EMB];
__device__ __align__(16) __half g_weh[WSUM];
__device__ __align__(16) __half g_wel[WSUM];
__device__ __align__(16) __half g_wd[WSUM];
__device__ __align__(16) __half g_ch[K_CENT * D_EMB];
__device__ __align__(16) __half g_cl[K_CENT * D_EMB];
__device__ __align__(16) float  g_S[(size_t)B_ROWS * K_CENT];
__device__ float g_c2[K_CENT];

// ---------------- helpers ----------------
__device__ __forceinline__ uint32_t smem_u32(const void* p) {
    uint32_t a;
    asm("{ .reg .u64 t; cvta.to.shared.u64 t, %1; cvt.u32.u64 %0, t; }" : "=r"(a) : "l"(p));
    return a;
}
__device__ __forceinline__ void split_fp16(float v, __half& h, __half& l) {
    h = __float2half_rn(v);
    l = __float2half_rn(v - __half2float(h));
}
__device__ __forceinline__ void mma_fp16(float* d, const uint32_t* a, const uint32_t* b) {
    asm volatile(
        "mma.sync.aligned.m16n8k16.row.col.f32.f16.f16.f32 "
        "{%0,%1,%2,%3}, {%4,%5,%6,%7}, {%8,%9}, {%0,%1,%2,%3};"
        : "+f"(d[0]), "+f"(d[1]), "+f"(d[2]), "+f"(d[3])
        : "r"(a[0]), "r"(a[1]), "r"(a[2]), "r"(a[3]), "r"(b[0]), "r"(b[1]));
}
#define LDSM_X4(r0, r1, r2, r3, addr) \
    asm volatile("ldmatrix.sync.aligned.m8n8.x4.shared.b16 {%0,%1,%2,%3}, [%4];" \
                 : "=r"(r0), "=r"(r1), "=r"(r2), "=r"(r3) : "r"(addr))
#define CP16(smaddr, gptr) \
    asm volatile("cp.async.cg.shared.global [%0], [%1], 16;" :: "r"(smaddr), "l"(gptr) : "memory")
#define CP_COMMIT() asm volatile("cp.async.commit_group;" ::: "memory")
#define CP_WAIT(n)  asm volatile("cp.async.wait_group %0;" :: "n"(n) : "memory")

// ===========================================================================
// Encoder GEMM: fp16x3 (hh+hl+lh), ldmatrix loads, chunked-sum fold/2,
// single-sync multistage pipeline (3 stages, prologue fills 2).
// Tile 128x64, 8 warps (32x32), BK=32, 2 CTAs/SM.
// ===========================================================================
#define FP16E_SMEM (3 * 30720)

__global__ void __launch_bounds__(256, 2)
gemm_fp16e(const __half* __restrict__ Ah, const __half* __restrict__ Al,
           const __half* __restrict__ Bh, const __half* __restrict__ Bl,
           const float* __restrict__ bias,
           float* __restrict__ outF, __half* __restrict__ outH, __half* __restrict__ outL,
           int M, int N, int K, int doRelu)
{
    extern __shared__ __half smh[];
    const int tid  = threadIdx.x;
    const int lane = tid & 31, wid = tid >> 5;
    const int g = lane >> 2, q = lane & 3;
    const int warpM = (wid & 3) * 32, warpN = (wid >> 2) * 32;
    const int brow = blockIdx.y * 128, bcol = blockIdx.x * 64;
    const int nch = K >> 5;
    const uint32_t smb = smem_u32(smh);
    const uint32_t laneOff = (uint32_t)((lane & 15) * 80 + (lane >> 4) * 16);

    float sum[2][4][4], acc[2][4][4];
    #pragma unroll
    for (int i = 0; i < 2; i++)
        #pragma unroll
        for (int j = 0; j < 4; j++)
            #pragma unroll
            for (int r = 0; r < 4; r++) { sum[i][j][r] = 0.f; acc[i][j][r] = 0.f; }

    const __half* gpA[2] = {Ah, Al};
    const __half* gpB[2] = {Bh, Bl};

    auto issue = [&](int ch, int s) {
        int kt = ch << 5;
        uint32_t sbase = smb + (uint32_t)s * 30720u;
        #pragma unroll
        for (int a = 0; a < 2; a++) {
            uint32_t base = sbase + (uint32_t)a * 10240u;
            #pragma unroll
            for (int it = 0; it < 2; it++) {
                int id = it * 256 + tid;
                int row = id >> 2, seg = id & 3;
                CP16(base + (uint32_t)(row * 80 + seg * 16),
                     gpA[a] + (size_t)(brow + row) * K + kt + seg * 8);
            }
        }
        #pragma unroll
        for (int a = 0; a < 2; a++) {
            uint32_t base = sbase + 20480u + (uint32_t)a * 5120u;
            int row = tid >> 2, seg = tid & 3;
            CP16(base + (uint32_t)(row * 80 + seg * 16),
                 gpB[a] + (size_t)(bcol + row) * K + kt + seg * 8);
        }
        CP_COMMIT();
    };

    // prologue: fill 2 of 3 stages
    issue(0, 0);
    if (nch > 1) issue(1, 1); else CP_COMMIT();

    for (int c = 0; c < nch; c++) {
        int s = c % 3;
        CP_WAIT(1);           // chunk c complete (newest pending is c+1)
        __syncthreads();      // all warps done with stage (c-1)%3 reads
        if (c + 2 < nch) issue(c + 2, (c + 2) % 3);   // = stage (c-1)%3

        uint32_t sbase = smb + (uint32_t)s * 30720u;
        uint32_t aAh = sbase + (uint32_t)(warpM * 80) + laneOff;
        uint32_t aAl = aAh + 10240u;
        uint32_t aBh = sbase + 20480u + (uint32_t)(warpN * 80) + laneOff;
        uint32_t aBl = aBh + 5120u;

        #pragma unroll
        for (int kb = 0; kb < 2; kb++) {
            uint32_t ko = (uint32_t)(kb * 32);
            uint32_t ah[2][4], al[2][4];
            #pragma unroll
            for (int i = 0; i < 2; i++) {
                LDSM_X4(ah[i][0], ah[i][1], ah[i][2], ah[i][3], aAh + ko + (uint32_t)(i * 16 * 80));
                LDSM_X4(al[i][0], al[i][1], al[i][2], al[i][3], aAl + ko + (uint32_t)(i * 16 * 80));
            }
            #pragma unroll
            for (int p = 0; p < 2; p++) {
                uint32_t bh4[4], bl4[4];
                LDSM_X4(bh4[0], bh4[1], bh4[2], bh4[3], aBh + ko + (uint32_t)(p * 16 * 80));
                LDSM_X4(bl4[0], bl4[1], bl4[2], bl4[3], aBl + ko + (uint32_t)(p * 16 * 80));
                uint32_t bfh0[2] = {bh4[0], bh4[2]}, bfh1[2] = {bh4[1], bh4[3]};
                uint32_t bfl0[2] = {bl4[0], bl4[2]}, bfl1[2] = {bl4[1], bl4[3]};
                #pragma unroll
                for (int i = 0; i < 2; i++) {
                    mma_fp16(acc[i][p * 2 + 0], ah[i], bfh0);
                    mma_fp16(acc[i][p * 2 + 1], ah[i], bfh1);
                }
                #pragma unroll
                for (int i = 0; i < 2; i++) {
                    mma_fp16(acc[i][p * 2 + 0], ah[i], bfl0);
                    mma_fp16(acc[i][p * 2 + 1], ah[i], bfl1);
                }
                #pragma unroll
                for (int i = 0; i < 2; i++) {
                    mma_fp16(acc[i][p * 2 + 0], al[i], bfh0);
                    mma_fp16(acc[i][p * 2 + 1], al[i], bfh1);
                }
            }
        }

        if ((c & 1) || c == nch - 1) {
            #pragma unroll
            for (int i = 0; i < 2; i++)
                #pragma unroll
                for (int j = 0; j < 4; j++)
                    #pragma unroll
                    for (int r = 0; r < 4; r++) {
                        sum[i][j][r] += acc[i][j][r];
                        acc[i][j][r] = 0.f;
                    }
        }
    }

    #pragma unroll
    for (int i = 0; i < 2; i++) {
        int r0 = brow + warpM + i * 16 + g;
        #pragma unroll
        for (int j = 0; j < 4; j++) {
            int col = bcol + warpN + j * 8 + 2 * q;
            float b0 = 0.f, b1 = 0.f;
            if (bias) { b0 = __ldg(bias + col); b1 = __ldg(bias + col + 1); }
            float v00 = sum[i][j][0] + b0;
            float v01 = sum[i][j][1] + b1;
            float v10 = sum[i][j][2] + b0;
            float v11 = sum[i][j][3] + b1;
            if (doRelu) {
                v00 = fmaxf(v00, 0.f); v01 = fmaxf(v01, 0.f);
                v10 = fmaxf(v10, 0.f); v11 = fmaxf(v11, 0.f);
            }
            size_t o0 = (size_t)r0 * N + col, o1 = o0 + 8 * (size_t)N;
            if (outF) {
                *reinterpret_cast<float2*>(outF + o0) = make_float2(v00, v01);
                *reinterpret_cast<float2*>(outF + o1) = make_float2(v10, v11);
            }
            if (outH) {
                __half h[4], l[4];
                split_fp16(v00, h[0], l[0]); split_fp16(v01, h[1], l[1]);
                split_fp16(v10, h[2], l[2]); split_fp16(v11, h[3], l[3]);
                *reinterpret_cast<__half2*>(outH + o0) = __halves2half2(h[0], h[1]);
                *reinterpret_cast<__half2*>(outH + o1) = __halves2half2(h[2], h[3]);
                *reinterpret_cast<__half2*>(outL + o0) = __halves2half2(l[0], l[1]);
                *reinterpret_cast<__half2*>(outL + o1) = __halves2half2(l[2], l[3]);
            }
        }
    }
}

// ===========================================================================
// Decoder GEMM: fp16x1, single-sync multistage, 3 CTAs/SM.
// Stage bytes: A 10240 | W 5120 = 15360.
// ===========================================================================
#define FP16S_SMEM (3 * 15360)

__global__ void __launch_bounds__(256, 3)
gemm_fp16s(const __half* __restrict__ A, const __half* __restrict__ W,
           const float* __restrict__ bias,
           float* __restrict__ outF, __half* __restrict__ outH,
           int M, int N, int K, int doRelu)
{
    extern __shared__ __half smh[];
    const int tid  = threadIdx.x;
    const int lane = tid & 31, wid = tid >> 5;
    const int g = lane >> 2, q = lane & 3;
    const int warpM = (wid & 3) * 32, warpN = (wid >> 2) * 32;
    const int brow = blockIdx.y * 128, bcol = blockIdx.x * 64;
    const int nch = K >> 5;
    const uint32_t smb = smem_u32(smh);
    const uint32_t laneOff = (uint32_t)((lane & 15) * 80 + (lane >> 4) * 16);

    float acc[2][4][4];
    #pragma unroll
    for (int i = 0; i < 2; i++)
        #pragma unroll
        for (int j = 0; j < 4; j++)
            #pragma unroll
            for (int r = 0; r < 4; r++) acc[i][j][r] = 0.f;

    auto issue = [&](int ch, int s) {
        int kt = ch << 5;
        uint32_t sbase = smb + (uint32_t)s * 15360u;
        #pragma unroll
        for (int it = 0; it < 2; it++) {
            int id = it * 256 + tid;
            int row = id >> 2, seg = id & 3;
            CP16(sbase + (uint32_t)(row * 80 + seg * 16),
                 A + (size_t)(brow + row) * K + kt + seg * 8);
        }
        {
            uint32_t base = sbase + 10240u;
            int row = tid >> 2, seg = tid & 3;
            CP16(base + (uint32_t)(row * 80 + seg * 16),
                 W + (size_t)(bcol + row) * K + kt + seg * 8);
        }
        CP_COMMIT();
    };

    issue(0, 0);
    if (nch > 1) issue(1, 1); else CP_COMMIT();

    for (int c = 0; c < nch; c++) {
        int s = c % 3;
        CP_WAIT(1);
        __syncthreads();
        if (c + 2 < nch) issue(c + 2, (c + 2) % 3);

        uint32_t sbase = smb + (uint32_t)s * 15360u;
        uint32_t aA = sbase + (uint32_t)(warpM * 80) + laneOff;
        uint32_t aW = sbase + 10240u + (uint32_t)(warpN * 80) + laneOff;

        #pragma unroll
        for (int kb = 0; kb < 2; kb++) {
            uint32_t ko = (uint32_t)(kb * 32);
            uint32_t a4[2][4];
            #pragma unroll
            for (int i = 0; i < 2; i++)
                LDSM_X4(a4[i][0], a4[i][1], a4[i][2], a4[i][3], aA + ko + (uint32_t)(i * 16 * 80));
            #pragma unroll
            for (int p = 0; p < 2; p++) {
                uint32_t w4[4];
                LDSM_X4(w4[0], w4[1], w4[2], w4[3], aW + ko + (uint32_t)(p * 16 * 80));
                uint32_t bf0[2] = {w4[0], w4[2]}, bf1[2] = {w4[1], w4[3]};
                #pragma unroll
                for (int i = 0; i < 2; i++) {
                    mma_fp16(acc[i][p * 2 + 0], a4[i], bf0);
                    mma_fp16(acc[i][p * 2 + 1], a4[i], bf1);
                }
            }
        }
    }

    #pragma unroll
    for (int i = 0; i < 2; i++) {
        int r0 = brow + warpM + i * 16 + g;
        #pragma unroll
        for (int j = 0; j < 4; j++) {
            int col = bcol + warpN + j * 8 + 2 * q;
            float b0 = 0.f, b1 = 0.f;
            if (bias) { b0 = __ldg(bias + col); b1 = __ldg(bias + col + 1); }
            float v00 = acc[i][j][0] + b0, v01 = acc[i][j][1] + b1;
            float v10 = acc[i][j][2] + b0, v11 = acc[i][j][3] + b1;
            if (doRelu) {
                v00 = fmaxf(v00, 0.f); v01 = fmaxf(v01, 0.f);
                v10 = fmaxf(v10, 0.f); v11 = fmaxf(v11, 0.f);
            }
            size_t o0 = (size_t)r0 * N + col, o1 = o0 + 8 * (size_t)N;
            if (outF) {
                *reinterpret_cast<float2*>(outF + o0) = make_float2(v00, v01);
                *reinterpret_cast<float2*>(outF + o1) = make_float2(v10, v11);
            }
            if (outH) {
                *reinterpret_cast<__half2*>(outH + o0) =
                    __halves2half2(__float2half_rn(v00), __float2half_rn(v01));
                *reinterpret_cast<__half2*>(outH + o1) =
                    __halves2half2(__float2half_rn(v10), __float2half_rn(v11));
            }
        }
    }
}

// ---------------- prep kernels ----------------
__global__ void vec_split_fp16(const float* __restrict__ a,
                               __half* __restrict__ hi, __half* __restrict__ lo, int n2)
{
    int i = blockIdx.x * blockDim.x + threadIdx.x;
    if (i >= n2) return;
    float2 v = reinterpret_cast<const float2*>(a)[i];
    __half hx, lx, hy, ly;
    split_fp16(v.x, hx, lx); split_fp16(v.y, hy, ly);
    reinterpret_cast<__half2*>(hi)[i] = __halves2half2(hx, hy);
    reinterpret_cast<__half2*>(lo)[i] = __halves2half2(lx, ly);
}

__global__ void wt_split_fp16(const float* __restrict__ W, __half* __restrict__ hi,
                              __half* __restrict__ lo, int Kd, int N)
{
    __shared__ float t[32][33];
    int bx = blockIdx.x * 32, by = blockIdx.y * 32;
    for (int i = threadIdx.y; i < 32; i += 8)
        t[i][threadIdx.x] = W[(size_t)(by + i) * N + bx + threadIdx.x];
    __syncthreads();
    for (int i = threadIdx.y; i < 32; i += 8) {
        float v = t[threadIdx.x][i];
        __half h, l;
        split_fp16(v, h, l);
        size_t o = (size_t)(bx + i) * Kd + by + threadIdx.x;
        hi[o] = h; lo[o] = l;
    }
}

__global__ void wt_single_fp16(const float* __restrict__ W, __half* __restrict__ out,
                               int Kd, int N)
{
    __shared__ float t[32][33];
    int bx = blockIdx.x * 32, by = blockIdx.y * 32;
    for (int i = threadIdx.y; i < 32; i += 8)
        t[i][threadIdx.x] = W[(size_t)(by + i) * N + bx + threadIdx.x];
    __syncthreads();
    for (int i = threadIdx.y; i < 32; i += 8)
        out[(size_t)(bx + i) * Kd + by + threadIdx.x] = __float2half_rn(t[threadIdx.x][i]);
}

__global__ void c2_kernel(const float* __restrict__ c, float* __restrict__ c2)
{
    int k = blockIdx.x * 8 + (threadIdx.x >> 5);
    int lane = threadIdx.x & 31;
    float s = 0.0f;
    for (int d = lane; d < D_EMB; d += 32) {
        float v = c[(size_t)k * D_EMB + d];
        s = fmaf(v, v, s);
    }
    #pragma unroll
    for (int o = 16; o; o >>= 1) s += __shfl_xor_sync(0xFFFFFFFFu, s, o);
    if (lane == 0) c2[k] = s;
}

__global__ void argmin_labels(const float* __restrict__ emb, const float* __restrict__ S,
                              const float* __restrict__ c2, float* __restrict__ labels)
{
    const int row = blockIdx.x, tid = threadIdx.x;
    __shared__ float red[256];
    float v = emb[(size_t)row * D_EMB + tid];
    red[tid] = v * v;
    __syncthreads();
    #pragma unroll
    for (int s = 128; s > 0; s >>= 1) {
        if (tid < s) red[tid] += red[tid + s];
        __syncthreads();
    }
    const float e2 = red[0];
    __syncthreads();
    float best = 3.402823466e38f;
    int bi = 0;
    for (int k = tid; k < K_CENT; k += 256) {
        float d = fmaxf(e2 + c2[k] - 2.0f * S[(size_t)row * K_CENT + k], 0.0f);
        if (d < best) { best = d; bi = k; }
    }
    __shared__ float sv[256];
    __shared__ int si[256];
    sv[tid] = best; si[tid] = bi;
    __syncthreads();
    #pragma unroll
    for (int s = 128; s > 0; s >>= 1) {
        if (tid < s) {
            float v2 = sv[tid + s]; int i2 = si[tid + s];
            if (v2 < sv[tid] || (v2 == sv[tid] && i2 < si[tid])) { sv[tid] = v2; si[tid] = i2; }
        }
        __syncthreads();
    }
    const int win = si[0];
    for (int k = tid; k < K_CENT; k += 256)
        labels[(size_t)row * K_CENT + k] = (k == win) ? 1.0f : 0.0f;
}

// ---------------- host launcher ----------------
extern "C" void kernel_launch(void* const* d_in, const int* in_sizes, int n_in,
                              void* d_out, int out_size)
{
    (void)in_sizes; (void)n_in; (void)out_size;

    cudaFuncSetAttribute(gemm_fp16e, cudaFuncAttributeMaxDynamicSharedMemorySize, FP16E_SMEM);
    cudaFuncSetAttribute(gemm_fp16s, cudaFuncAttributeMaxDynamicSharedMemorySize, FP16S_SMEM);

    const float* x = (const float*)d_in[0];
    const float* W[8]  = {(const float*)d_in[1],  (const float*)d_in[3],
                          (const float*)d_in[5],  (const float*)d_in[7],
                          (const float*)d_in[9],  (const float*)d_in[11],
                          (const float*)d_in[13], (const float*)d_in[15]};
    const float* bv[8] = {(const float*)d_in[2],  (const float*)d_in[4],
                          (const float*)d_in[6],  (const float*)d_in[8],
                          (const float*)d_in[10], (const float*)d_in[12],
                          (const float*)d_in[14], (const float*)d_in[16]};
    const float* centers = (const float*)d_in[17];

    float* out    = (float*)d_out;
    float* recon  = out;
    float* emb    = out + (size_t)B_ROWS * D_IN;
    float* labels = emb + (size_t)B_ROWS * D_EMB;

    __half *xh, *xl, *h0h, *h0l, *h1h, *h1l, *eh, *el, *weh, *wel, *wd, *ch, *cl;
    float *S, *c2;
    cudaGetSymbolAddress((void**)&xh, g_xh);   cudaGetSymbolAddress((void**)&xl, g_xl);
    cudaGetSymbolAddress((void**)&h0h, g_h0h); cudaGetSymbolAddress((void**)&h0l, g_h0l);
    cudaGetSymbolAddress((void**)&h1h, g_h1h); cudaGetSymbolAddress((void**)&h1l, g_h1l);
    cudaGetSymbolAddress((void**)&eh, g_eh);   cudaGetSymbolAddress((void**)&el, g_el);
    cudaGetSymbolAddress((void**)&weh, g_weh); cudaGetSymbolAddress((void**)&wel, g_wel);
    cudaGetSymbolAddress((void**)&wd, g_wd);
    cudaGetSymbolAddress((void**)&ch, g_ch);   cudaGetSymbolAddress((void**)&cl, g_cl);
    cudaGetSymbolAddress((void**)&S, g_S);     cudaGetSymbolAddress((void**)&c2, g_c2);

    const int fi[8] = {1024, 2048, 1024, 512, 256, 512, 1024, 2048};
    const int fo[8] = {2048, 1024, 512, 256, 512, 1024, 2048, 1024};
    size_t off[8], acc = 0, accd = 0;
    for (int i = 0; i < 4; i++) { off[i] = acc;  acc  += (size_t)fi[i] * fo[i]; }
    for (int i = 4; i < 8; i++) { off[i] = accd; accd += (size_t)fi[i] * fo[i]; }

    auto wenc = [&](int i) {
        dim3 g(fo[i] / 32, fi[i] / 32), b(32, 8);
        wt_split_fp16<<<g, b>>>(W[i], weh + off[i], wel + off[i], fi[i], fo[i]);
    };

    c2_kernel<<<K_CENT / 8, 256>>>(centers, c2);                               // 1
    vec_split_fp16<<<(B_ROWS * D_IN / 2 + 255) / 256, 256>>>(x, xh, xl,
                                                             B_ROWS * D_IN / 2); // 2
    wenc(0);                                                                   // 3
    {
        dim3 g0(2048 / 64, B_ROWS / 128);                                      // 4
        gemm_fp16e<<<g0, 256, FP16E_SMEM>>>(xh, xl, weh + off[0], wel + off[0], bv[0],
                                            nullptr, h0h, h0l, B_ROWS, 2048, 1024, 1);
    }
    wenc(1);                                                                   // 5
    {
        dim3 g1(1024 / 64, B_ROWS / 128);                                      // 6
        gemm_fp16e<<<g1, 256, FP16E_SMEM>>>(h0h, h0l, weh + off[1], wel + off[1], bv[1],
                                            nullptr, h1h, h1l, B_ROWS, 1024, 2048, 1);
    }
    wenc(2);
    {
        dim3 g2(512 / 64, B_ROWS / 128);
        gemm_fp16e<<<g2, 256, FP16E_SMEM>>>(h1h, h1l, weh + off[2], wel + off[2], bv[2],
                                            nullptr, h0h, h0l, B_ROWS, 512, 1024, 1);
    }
    wenc(3);
    {
        dim3 g3(256 / 64, B_ROWS / 128);
        gemm_fp16e<<<g3, 256, FP16E_SMEM>>>(h0h, h0l, weh + off[3], wel + off[3], bv[3],
                                            emb, eh, el, B_ROWS, 256, 512, 0);
    }

    vec_split_fp16<<<(K_CENT * D_EMB / 2 + 255) / 256, 256>>>(centers, ch, cl,
                                                              K_CENT * D_EMB / 2);
    {
        dim3 g(K_CENT / 64, B_ROWS / 128);
        gemm_fp16e<<<g, 256, FP16E_SMEM>>>(eh, el, ch, cl, nullptr,
                                           S, nullptr, nullptr, B_ROWS, K_CENT, D_EMB, 0);
    }
    argmin_labels<<<B_ROWS, 256>>>(emb, S, c2, labels);

    for (int i = 4; i < 8; i++) {
        dim3 g(fo[i] / 32, fi[i] / 32), b(32, 8);
        wt_single_fp16<<<g, b>>>(W[i], wd + off[i], fi[i], fo[i]);
    }
    {
        dim3 g0(512 / 64, B_ROWS / 128);
        gemm_fp16s<<<g0, 256, FP16S_SMEM>>>(eh, wd + off[4], bv[4],
                                            nullptr, h0h, B_ROWS, 512, 256, 1);
        dim3 g1(1024 / 64, B_ROWS / 128);
        gemm_fp16s<<<g1, 256, FP16S_SMEM>>>(h0h, wd + off[5], bv[5],
                                            nullptr, h1h, B_ROWS, 1024, 512, 1);
        dim3 g2(2048 / 64, B_ROWS / 128);
        gemm_fp16s<<<g2, 256, FP16S_SMEM>>>(h1h, wd + off[6], bv[6],
                                            nullptr, h0h, B_ROWS, 2048, 1024, 1);
        dim3 g3(1024 / 64, B_ROWS / 128);
        gemm_fp16s<<<g3, 256, FP16S_SMEM>>>(h0h, wd + off[7], bv[7],
                                            recon, nullptr, B_ROWS, 1024, 2048, 0);
    }
}

// round 14
// speedup vs baseline: 1.7727x; 1.3075x over previous
#include <cuda_runtime.h>
#include <cuda_fp16.h>
#include <cstdint>
#include <cstddef>

#define B_ROWS 8192
#define D_IN   1024
#define D_EMB  256
#define K_CENT 1024
#define WSUM   4849664

// ---------------- device scratch ----------------
__device__ __align__(16) __half g_xh[(size_t)B_ROWS * D_IN];
__device__ __align__(16) __half g_xl[(size_t)B_ROWS * D_IN];
__device__ __align__(16) __half g_h0h[(size_t)B_ROWS * 2048];
__device__ __align__(16) __half g_h0l[(size_t)B_ROWS * 2048];
__device__ __align__(16) __half g_h1h[(size_t)B_ROWS * 2048];
__device__ __align__(16) __half g_h1l[(size_t)B_ROWS * 2048];
__device__ __align__(16) __half g_eh[(size_t)B_ROWS * D_EMB];
__device__ __align__(16) __half g_el[(size_t)B_ROWS * D_EMB];
__device__ __align__(16) __half g_weh[WSUM];
__device__ __align__(16) __half g_wel[WSUM];
__device__ __align__(16) __half g_wd[WSUM];
__device__ __align__(16) __half g_ch[K_CENT * D_EMB];
__device__ __align__(16) __half g_cl[K_CENT * D_EMB];
__device__ __align__(16) float  g_S[(size_t)B_ROWS * K_CENT];
__device__ float g_c2[K_CENT];

// ---------------- helpers ----------------
__device__ __forceinline__ uint32_t smem_u32(const void* p) {
    uint32_t a;
    asm("{ .reg .u64 t; cvta.to.shared.u64 t, %1; cvt.u32.u64 %0, t; }" : "=r"(a) : "l"(p));
    return a;
}
__device__ __forceinline__ void split_fp16(float v, __half& h, __half& l) {
    h = __float2half_rn(v);
    l = __float2half_rn(v - __half2float(h));
}
__device__ __forceinline__ void mma_fp16(float* d, const uint32_t* a, const uint32_t* b) {
    asm volatile(
        "mma.sync.aligned.m16n8k16.row.col.f32.f16.f16.f32 "
        "{%0,%1,%2,%3}, {%4,%5,%6,%7}, {%8,%9}, {%0,%1,%2,%3};"
        : "+f"(d[0]), "+f"(d[1]), "+f"(d[2]), "+f"(d[3])
        : "r"(a[0]), "r"(a[1]), "r"(a[2]), "r"(a[3]), "r"(b[0]), "r"(b[1]));
}
#define LDSM_X4(r0, r1, r2, r3, addr) \
    asm volatile("ldmatrix.sync.aligned.m8n8.x4.shared.b16 {%0,%1,%2,%3}, [%4];" \
                 : "=r"(r0), "=r"(r1), "=r"(r2), "=r"(r3) : "r"(addr))
#define CP16(smaddr, gptr) \
    asm volatile("cp.async.cg.shared.global [%0], [%1], 16;" :: "r"(smaddr), "l"(gptr) : "memory")
#define CP_COMMIT() asm volatile("cp.async.commit_group;" ::: "memory")
#define CP_WAIT(n)  asm volatile("cp.async.wait_group %0;" :: "n"(n) : "memory")

#define SWZ(off) ((off) ^ (((off) >> 3) & 0x70u))

// ===========================================================================
// Encoder GEMM: fp16x3 (hh+hl+lh), BK=64 chunks, SW128-swizzled smem
// (128 B rows, no padding), ldmatrix with per-lane folded swizzle constants.
// Tile 128x64, 8 warps (32x32), 2 stages, 2 CTAs/SM.
// Stage: Ah 16384 | Al 16384 | Bh 8192 | Bl 8192 = 49152 B.
// ===========================================================================
#define FP16E_SMEM (2 * 49152)

__global__ void __launch_bounds__(256, 2)
gemm_fp16e(const __half* __restrict__ Ah, const __half* __restrict__ Al,
           const __half* __restrict__ Bh, const __half* __restrict__ Bl,
           const float* __restrict__ bias,
           float* __restrict__ outF, __half* __restrict__ outH, __half* __restrict__ outL,
           int M, int N, int K, int doRelu)
{
    extern __shared__ __half smh[];
    const int tid  = threadIdx.x;
    const int lane = tid & 31, wid = tid >> 5;
    const int g = lane >> 2, q = lane & 3;
    const int warpM = (wid & 3) * 32, warpN = (wid >> 2) * 32;
    const int brow = blockIdx.y * 128, bcol = blockIdx.x * 64;
    const int nch = K >> 6;                 // BK = 64
    const uint32_t smb = smem_u32(smh);

    // ldmatrix lane geometry (swizzle XOR folds into per-lane constants)
    const uint32_t laneRowB = (uint32_t)((lane & 15) * 128);
    const uint32_t laneColC = (uint32_t)((lane >> 4) * 16);
    const uint32_t xorC     = (uint32_t)((lane & 7) * 16);
    uint32_t kcol[4];
    #pragma unroll
    for (int kb = 0; kb < 4; kb++) kcol[kb] = (laneColC + (uint32_t)(kb * 32)) ^ xorC;

    // cp.async per-thread store offsets (swizzled), 128 B rows
    // A arrays: 4 iters x (row = id>>3, seg = id&7); B arrays: 2 iters.
    float sum[2][4][4], acc[2][4][4];
    #pragma unroll
    for (int i = 0; i < 2; i++)
        #pragma unroll
        for (int j = 0; j < 4; j++)
            #pragma unroll
            for (int r = 0; r < 4; r++) { sum[i][j][r] = 0.f; acc[i][j][r] = 0.f; }

    const __half* gpA[2] = {Ah, Al};
    const __half* gpB[2] = {Bh, Bl};

    auto issue = [&](int ch, int s) {
        int kt = ch << 6;
        uint32_t sbase = smb + (uint32_t)s * 49152u;
        #pragma unroll
        for (int a = 0; a < 2; a++) {
            uint32_t base = sbase + (uint32_t)a * 16384u;
            #pragma unroll
            for (int it = 0; it < 4; it++) {
                int id = it * 256 + tid;
                uint32_t row = (uint32_t)(id >> 3), seg = (uint32_t)(id & 7);
                uint32_t off = row * 128u + seg * 16u;
                CP16(base + SWZ(off),
                     gpA[a] + (size_t)(brow + (int)row) * K + kt + (int)seg * 8);
            }
        }
        #pragma unroll
        for (int a = 0; a < 2; a++) {
            uint32_t base = sbase + 32768u + (uint32_t)a * 8192u;
            #pragma unroll
            for (int it = 0; it < 2; it++) {
                int id = it * 256 + tid;
                uint32_t row = (uint32_t)(id >> 3), seg = (uint32_t)(id & 7);
                uint32_t off = row * 128u + seg * 16u;
                CP16(base + SWZ(off),
                     gpB[a] + (size_t)(bcol + (int)row) * K + kt + (int)seg * 8);
            }
        }
        CP_COMMIT();
    };

    issue(0, 0);
    if (nch > 1) issue(1, 1);

    for (int c = 0; c < nch; c++) {
        int s = c & 1;
        if (c + 1 < nch) { CP_WAIT(1); } else { CP_WAIT(0); }
        __syncthreads();

        uint32_t sbase = smb + (uint32_t)s * 49152u;
        uint32_t aAh = sbase + (uint32_t)(warpM * 128) + laneRowB;
        uint32_t aAl = aAh + 16384u;
        uint32_t aBh = sbase + 32768u + (uint32_t)(warpN * 128) + laneRowB;
        uint32_t aBl = aBh + 8192u;

        #pragma unroll
        for (int kb = 0; kb < 4; kb++) {
            uint32_t ko = kcol[kb];
            uint32_t ah[2][4], al[2][4];
            #pragma unroll
            for (int i = 0; i < 2; i++) {
                LDSM_X4(ah[i][0], ah[i][1], ah[i][2], ah[i][3], aAh + ko + (uint32_t)(i * 2048));
                LDSM_X4(al[i][0], al[i][1], al[i][2], al[i][3], aAl + ko + (uint32_t)(i * 2048));
            }
            #pragma unroll
            for (int p = 0; p < 2; p++) {
                uint32_t bh4[4], bl4[4];
                LDSM_X4(bh4[0], bh4[1], bh4[2], bh4[3], aBh + ko + (uint32_t)(p * 2048));
                LDSM_X4(bl4[0], bl4[1], bl4[2], bl4[3], aBl + ko + (uint32_t)(p * 2048));
                uint32_t bfh0[2] = {bh4[0], bh4[2]}, bfh1[2] = {bh4[1], bh4[3]};
                uint32_t bfl0[2] = {bl4[0], bl4[2]}, bfl1[2] = {bl4[1], bl4[3]};
                #pragma unroll
                for (int i = 0; i < 2; i++) {
                    mma_fp16(acc[i][p * 2 + 0], ah[i], bfh0);
                    mma_fp16(acc[i][p * 2 + 1], ah[i], bfh1);
                }
                #pragma unroll
                for (int i = 0; i < 2; i++) {
                    mma_fp16(acc[i][p * 2 + 0], ah[i], bfl0);
                    mma_fp16(acc[i][p * 2 + 1], ah[i], bfl1);
                }
                #pragma unroll
                for (int i = 0; i < 2; i++) {
                    mma_fp16(acc[i][p * 2 + 0], al[i], bfh0);
                    mma_fp16(acc[i][p * 2 + 1], al[i], bfh1);
                }
            }
        }

        // fold per BK=64 chunk (same span as R12's fold-per-2)
        #pragma unroll
        for (int i = 0; i < 2; i++)
            #pragma unroll
            for (int j = 0; j < 4; j++)
                #pragma unroll
                for (int r = 0; r < 4; r++) {
                    sum[i][j][r] += acc[i][j][r];
                    acc[i][j][r] = 0.f;
                }

        __syncthreads();
        if (c + 2 < nch) issue(c + 2, s);
    }

    #pragma unroll
    for (int i = 0; i < 2; i++) {
        int r0 = brow + warpM + i * 16 + g;
        #pragma unroll
        for (int j = 0; j < 4; j++) {
            int col = bcol + warpN + j * 8 + 2 * q;
            float b0 = 0.f, b1 = 0.f;
            if (bias) { b0 = __ldg(bias + col); b1 = __ldg(bias + col + 1); }
            float v00 = sum[i][j][0] + b0;
            float v01 = sum[i][j][1] + b1;
            float v10 = sum[i][j][2] + b0;
            float v11 = sum[i][j][3] + b1;
            if (doRelu) {
                v00 = fmaxf(v00, 0.f); v01 = fmaxf(v01, 0.f);
                v10 = fmaxf(v10, 0.f); v11 = fmaxf(v11, 0.f);
            }
            size_t o0 = (size_t)r0 * N + col, o1 = o0 + 8 * (size_t)N;
            if (outF) {
                *reinterpret_cast<float2*>(outF + o0) = make_float2(v00, v01);
                *reinterpret_cast<float2*>(outF + o1) = make_float2(v10, v11);
            }
            if (outH) {
                __half h[4], l[4];
                split_fp16(v00, h[0], l[0]); split_fp16(v01, h[1], l[1]);
                split_fp16(v10, h[2], l[2]); split_fp16(v11, h[3], l[3]);
                *reinterpret_cast<__half2*>(outH + o0) = __halves2half2(h[0], h[1]);
                *reinterpret_cast<__half2*>(outH + o1) = __halves2half2(h[2], h[3]);
                *reinterpret_cast<__half2*>(outL + o0) = __halves2half2(l[0], l[1]);
                *reinterpret_cast<__half2*>(outL + o1) = __halves2half2(l[2], l[3]);
            }
        }
    }
}

// ===========================================================================
// Decoder GEMM: fp16x1, BK=64, swizzled smem, 2 stages, 3 CTAs/SM.
// Stage: A 16384 | W 8192 = 24576 B.
// ===========================================================================
#define FP16S_SMEM (2 * 24576)

__global__ void __launch_bounds__(256, 3)
gemm_fp16s(const __half* __restrict__ A, const __half* __restrict__ W,
           const float* __restrict__ bias,
           float* __restrict__ outF, __half* __restrict__ outH,
           int M, int N, int K, int doRelu)
{
    extern __shared__ __half smh[];
    const int tid  = threadIdx.x;
    const int lane = tid & 31, wid = tid >> 5;
    const int g = lane >> 2, q = lane & 3;
    const int warpM = (wid & 3) * 32, warpN = (wid >> 2) * 32;
    const int brow = blockIdx.y * 128, bcol = blockIdx.x * 64;
    const int nch = K >> 6;
    const uint32_t smb = smem_u32(smh);

    const uint32_t laneRowB = (uint32_t)((lane & 15) * 128);
    const uint32_t laneColC = (uint32_t)((lane >> 4) * 16);
    const uint32_t xorC     = (uint32_t)((lane & 7) * 16);
    uint32_t kcol[4];
    #pragma unroll
    for (int kb = 0; kb < 4; kb++) kcol[kb] = (laneColC + (uint32_t)(kb * 32)) ^ xorC;

    float acc[2][4][4];
    #pragma unroll
    for (int i = 0; i < 2; i++)
        #pragma unroll
        for (int j = 0; j < 4; j++)
            #pragma unroll
            for (int r = 0; r < 4; r++) acc[i][j][r] = 0.f;

    auto issue = [&](int ch, int s) {
        int kt = ch << 6;
        uint32_t sbase = smb + (uint32_t)s * 24576u;
        #pragma unroll
        for (int it = 0; it < 4; it++) {
            int id = it * 256 + tid;
            uint32_t row = (uint32_t)(id >> 3), seg = (uint32_t)(id & 7);
            uint32_t off = row * 128u + seg * 16u;
            CP16(sbase + SWZ(off),
                 A + (size_t)(brow + (int)row) * K + kt + (int)seg * 8);
        }
        {
            uint32_t base = sbase + 16384u;
            #pragma unroll
            for (int it = 0; it < 2; it++) {
                int id = it * 256 + tid;
                uint32_t row = (uint32_t)(id >> 3), seg = (uint32_t)(id & 7);
                uint32_t off = row * 128u + seg * 16u;
                CP16(base + SWZ(off),
                     W + (size_t)(bcol + (int)row) * K + kt + (int)seg * 8);
            }
        }
        CP_COMMIT();
    };

    issue(0, 0);
    if (nch > 1) issue(1, 1);

    for (int c = 0; c < nch; c++) {
        int s = c & 1;
        if (c + 1 < nch) { CP_WAIT(1); } else { CP_WAIT(0); }
        __syncthreads();

        uint32_t sbase = smb + (uint32_t)s * 24576u;
        uint32_t aA = sbase + (uint32_t)(warpM * 128) + laneRowB;
        uint32_t aW = sbase + 16384u + (uint32_t)(warpN * 128) + laneRowB;

        #pragma unroll
        for (int kb = 0; kb < 4; kb++) {
            uint32_t ko = kcol[kb];
            uint32_t a4[2][4];
            #pragma unroll
            for (int i = 0; i < 2; i++)
                LDSM_X4(a4[i][0], a4[i][1], a4[i][2], a4[i][3], aA + ko + (uint32_t)(i * 2048));
            #pragma unroll
            for (int p = 0; p < 2; p++) {
                uint32_t w4[4];
                LDSM_X4(w4[0], w4[1], w4[2], w4[3], aW + ko + (uint32_t)(p * 2048));
                uint32_t bf0[2] = {w4[0], w4[2]}, bf1[2] = {w4[1], w4[3]};
                #pragma unroll
                for (int i = 0; i < 2; i++) {
                    mma_fp16(acc[i][p * 2 + 0], a4[i], bf0);
                    mma_fp16(acc[i][p * 2 + 1], a4[i], bf1);
                }
            }
        }

        __syncthreads();
        if (c + 2 < nch) issue(c + 2, s);
    }

    #pragma unroll
    for (int i = 0; i < 2; i++) {
        int r0 = brow + warpM + i * 16 + g;
        #pragma unroll
        for (int j = 0; j < 4; j++) {
            int col = bcol + warpN + j * 8 + 2 * q;
            float b0 = 0.f, b1 = 0.f;
            if (bias) { b0 = __ldg(bias + col); b1 = __ldg(bias + col + 1); }
            float v00 = acc[i][j][0] + b0, v01 = acc[i][j][1] + b1;
            float v10 = acc[i][j][2] + b0, v11 = acc[i][j][3] + b1;
            if (doRelu) {
                v00 = fmaxf(v00, 0.f); v01 = fmaxf(v01, 0.f);
                v10 = fmaxf(v10, 0.f); v11 = fmaxf(v11, 0.f);
            }
            size_t o0 = (size_t)r0 * N + col, o1 = o0 + 8 * (size_t)N;
            if (outF) {
                *reinterpret_cast<float2*>(outF + o0) = make_float2(v00, v01);
                *reinterpret_cast<float2*>(outF + o1) = make_float2(v10, v11);
            }
            if (outH) {
                *reinterpret_cast<__half2*>(outH + o0) =
                    __halves2half2(__float2half_rn(v00), __float2half_rn(v01));
                *reinterpret_cast<__half2*>(outH + o1) =
                    __halves2half2(__float2half_rn(v10), __float2half_rn(v11));
            }
        }
    }
}

// ---------------- prep kernels ----------------
__global__ void vec_split_fp16(const float* __restrict__ a,
                               __half* __restrict__ hi, __half* __restrict__ lo, int n2)
{
    int i = blockIdx.x * blockDim.x + threadIdx.x;
    if (i >= n2) return;
    float2 v = reinterpret_cast<const float2*>(a)[i];
    __half hx, lx, hy, ly;
    split_fp16(v.x, hx, lx); split_fp16(v.y, hy, ly);
    reinterpret_cast<__half2*>(hi)[i] = __halves2half2(hx, hy);
    reinterpret_cast<__half2*>(lo)[i] = __halves2half2(lx, ly);
}

__global__ void wt_split_fp16(const float* __restrict__ W, __half* __restrict__ hi,
                              __half* __restrict__ lo, int Kd, int N)
{
    __shared__ float t[32][33];
    int bx = blockIdx.x * 32, by = blockIdx.y * 32;
    for (int i = threadIdx.y; i < 32; i += 8)
        t[i][threadIdx.x] = W[(size_t)(by + i) * N + bx + threadIdx.x];
    __syncthreads();
    for (int i = threadIdx.y; i < 32; i += 8) {
        float v = t[threadIdx.x][i];
        __half h, l;
        split_fp16(v, h, l);
        size_t o = (size_t)(bx + i) * Kd + by + threadIdx.x;
        hi[o] = h; lo[o] = l;
    }
}

__global__ void wt_single_fp16(const float* __restrict__ W, __half* __restrict__ out,
                               int Kd, int N)
{
    __shared__ float t[32][33];
    int bx = blockIdx.x * 32, by = blockIdx.y * 32;
    for (int i = threadIdx.y; i < 32; i += 8)
        t[i][threadIdx.x] = W[(size_t)(by + i) * N + bx + threadIdx.x];
    __syncthreads();
    for (int i = threadIdx.y; i < 32; i += 8)
        out[(size_t)(bx + i) * Kd + by + threadIdx.x] = __float2half_rn(t[threadIdx.x][i]);
}

__global__ void c2_kernel(const float* __restrict__ c, float* __restrict__ c2)
{
    int k = blockIdx.x * 8 + (threadIdx.x >> 5);
    int lane = threadIdx.x & 31;
    float s = 0.0f;
    for (int d = lane; d < D_EMB; d += 32) {
        float v = c[(size_t)k * D_EMB + d];
        s = fmaf(v, v, s);
    }
    #pragma unroll
    for (int o = 16; o; o >>= 1) s += __shfl_xor_sync(0xFFFFFFFFu, s, o);
    if (lane == 0) c2[k] = s;
}

__global__ void argmin_labels(const float* __restrict__ emb, const float* __restrict__ S,
                              const float* __restrict__ c2, float* __restrict__ labels)
{
    const int row = blockIdx.x, tid = threadIdx.x;
    __shared__ float red[256];
    float v = emb[(size_t)row * D_EMB + tid];
    red[tid] = v * v;
    __syncthreads();
    #pragma unroll
    for (int s = 128; s > 0; s >>= 1) {
        if (tid < s) red[tid] += red[tid + s];
        __syncthreads();
    }
    const float e2 = red[0];
    __syncthreads();
    float best = 3.402823466e38f;
    int bi = 0;
    for (int k = tid; k < K_CENT; k += 256) {
        float d = fmaxf(e2 + c2[k] - 2.0f * S[(size_t)row * K_CENT + k], 0.0f);
        if (d < best) { best = d; bi = k; }
    }
    __shared__ float sv[256];
    __shared__ int si[256];
    sv[tid] = best; si[tid] = bi;
    __syncthreads();
    #pragma unroll
    for (int s = 128; s > 0; s >>= 1) {
        if (tid < s) {
            float v2 = sv[tid + s]; int i2 = si[tid + s];
            if (v2 < sv[tid] || (v2 == sv[tid] && i2 < si[tid])) { sv[tid] = v2; si[tid] = i2; }
        }
        __syncthreads();
    }
    const int win = si[0];
    for (int k = tid; k < K_CENT; k += 256)
        labels[(size_t)row * K_CENT + k] = (k == win) ? 1.0f : 0.0f;
}

// ---------------- host launcher ----------------
extern "C" void kernel_launch(void* const* d_in, const int* in_sizes, int n_in,
                              void* d_out, int out_size)
{
    (void)in_sizes; (void)n_in; (void)out_size;

    cudaFuncSetAttribute(gemm_fp16e, cudaFuncAttributeMaxDynamicSharedMemorySize, FP16E_SMEM);
    cudaFuncSetAttribute(gemm_fp16s, cudaFuncAttributeMaxDynamicSharedMemorySize, FP16S_SMEM);

    const float* x = (const float*)d_in[0];
    const float* W[8]  = {(const float*)d_in[1],  (const float*)d_in[3],
                          (const float*)d_in[5],  (const float*)d_in[7],
                          (const float*)d_in[9],  (const float*)d_in[11],
                          (const float*)d_in[13], (const float*)d_in[15]};
    const float* bv[8] = {(const float*)d_in[2],  (const float*)d_in[4],
                          (const float*)d_in[6],  (const float*)d_in[8],
                          (const float*)d_in[10], (const float*)d_in[12],
                          (const float*)d_in[14], (const float*)d_in[16]};
    const float* centers = (const float*)d_in[17];

    float* out    = (float*)d_out;
    float* recon  = out;
    float* emb    = out + (size_t)B_ROWS * D_IN;
    float* labels = emb + (size_t)B_ROWS * D_EMB;

    __half *xh, *xl, *h0h, *h0l, *h1h, *h1l, *eh, *el, *weh, *wel, *wd, *ch, *cl;
    float *S, *c2;
    cudaGetSymbolAddress((void**)&xh, g_xh);   cudaGetSymbolAddress((void**)&xl, g_xl);
    cudaGetSymbolAddress((void**)&h0h, g_h0h); cudaGetSymbolAddress((void**)&h0l, g_h0l);
    cudaGetSymbolAddress((void**)&h1h, g_h1h); cudaGetSymbolAddress((void**)&h1l, g_h1l);
    cudaGetSymbolAddress((void**)&eh, g_eh);   cudaGetSymbolAddress((void**)&el, g_el);
    cudaGetSymbolAddress((void**)&weh, g_weh); cudaGetSymbolAddress((void**)&wel, g_wel);
    cudaGetSymbolAddress((void**)&wd, g_wd);
    cudaGetSymbolAddress((void**)&ch, g_ch);   cudaGetSymbolAddress((void**)&cl, g_cl);
    cudaGetSymbolAddress((void**)&S, g_S);     cudaGetSymbolAddress((void**)&c2, g_c2);

    const int fi[8] = {1024, 2048, 1024, 512, 256, 512, 1024, 2048};
    const int fo[8] = {2048, 1024, 512, 256, 512, 1024, 2048, 1024};
    size_t off[8], acc = 0, accd = 0;
    for (int i = 0; i < 4; i++) { off[i] = acc;  acc  += (size_t)fi[i] * fo[i]; }
    for (int i = 4; i < 8; i++) { off[i] = accd; accd += (size_t)fi[i] * fo[i]; }

    auto wenc = [&](int i) {
        dim3 g(fo[i] / 32, fi[i] / 32), b(32, 8);
        wt_split_fp16<<<g, b>>>(W[i], weh + off[i], wel + off[i], fi[i], fo[i]);
    };

    c2_kernel<<<K_CENT / 8, 256>>>(centers, c2);                               // 1
    vec_split_fp16<<<(B_ROWS * D_IN / 2 + 255) / 256, 256>>>(x, xh, xl,
                                                             B_ROWS * D_IN / 2); // 2
    wenc(0);                                                                   // 3
    {
        dim3 g0(2048 / 64, B_ROWS / 128);                                      // 4
        gemm_fp16e<<<g0, 256, FP16E_SMEM>>>(xh, xl, weh + off[0], wel + off[0], bv[0],
                                            nullptr, h0h, h0l, B_ROWS, 2048, 1024, 1);
    }
    wenc(1);                                                                   // 5
    {
        dim3 g1(1024 / 64, B_ROWS / 128);                                      // 6
        gemm_fp16e<<<g1, 256, FP16E_SMEM>>>(h0h, h0l, weh + off[1], wel + off[1], bv[1],
                                            nullptr, h1h, h1l, B_ROWS, 1024, 2048, 1);
    }
    wenc(2);
    {
        dim3 g2(512 / 64, B_ROWS / 128);
        gemm_fp16e<<<g2, 256, FP16E_SMEM>>>(h1h, h1l, weh + off[2], wel + off[2], bv[2],
                                            nullptr, h0h, h0l, B_ROWS, 512, 1024, 1);
    }
    wenc(3);
    {
        dim3 g3(256 / 64, B_ROWS / 128);
        gemm_fp16e<<<g3, 256, FP16E_SMEM>>>(h0h, h0l, weh + off[3], wel + off[3], bv[3],
                                            emb, eh, el, B_ROWS, 256, 512, 0);
    }

    vec_split_fp16<<<(K_CENT * D_EMB / 2 + 255) / 256, 256>>>(centers, ch, cl,
                                                              K_CENT * D_EMB / 2);
    {
        dim3 g(K_CENT / 64, B_ROWS / 128);
        gemm_fp16e<<<g, 256, FP16E_SMEM>>>(eh, el, ch, cl, nullptr,
                                           S, nullptr, nullptr, B_ROWS, K_CENT, D_EMB, 0);
    }
    argmin_labels<<<B_ROWS, 256>>>(emb, S, c2, labels);

    for (int i = 4; i < 8; i++) {
        dim3 g(fo[i] / 32, fi[i] / 32), b(32, 8);
        wt_single_fp16<<<g, b>>>(W[i], wd + off[i], fi[i], fo[i]);
    }
    {
        dim3 g0(512 / 64, B_ROWS / 128);
        gemm_fp16s<<<g0, 256, FP16S_SMEM>>>(eh, wd + off[4], bv[4],
                                            nullptr, h0h, B_ROWS, 512, 256, 1);
        dim3 g1(1024 / 64, B_ROWS / 128);
        gemm_fp16s<<<g1, 256, FP16S_SMEM>>>(h0h, wd + off[5], bv[5],
                                            nullptr, h1h, B_ROWS, 1024, 512, 1);
        dim3 g2(2048 / 64, B_ROWS / 128);
        gemm_fp16s<<<g2, 256, FP16S_SMEM>>>(h1h, wd + off[6], bv[6],
                                            nullptr, h0h, B_ROWS, 2048, 1024, 1);
        dim3 g3(1024 / 64, B_ROWS / 128);
        gemm_fp16s<<<g3, 256, FP16S_SMEM>>>(h0h, wd + off[7], bv[7],
                                            recon, nullptr, B_ROWS, 1024, 2048, 0);
    }
}

// round 15
// speedup vs baseline: 1.8162x; 1.0246x over previous
#include <cuda_runtime.h>
#include <cuda_fp16.h>
#include <cstdint>
#include <cstddef>

#define B_ROWS 8192
#define D_IN   1024
#define D_EMB  256
#define K_CENT 1024
#define WSUM   4849664

// ---------------- device scratch ----------------
__device__ __align__(16) __half g_xh[(size_t)B_ROWS * D_IN];
__device__ __align__(16) __half g_xl[(size_t)B_ROWS * D_IN];
__device__ __align__(16) __half g_h0h[(size_t)B_ROWS * 2048];
__device__ __align__(16) __half g_h0l[(size_t)B_ROWS * 2048];
__device__ __align__(16) __half g_h1h[(size_t)B_ROWS * 2048];
__device__ __align__(16) __half g_h1l[(size_t)B_ROWS * 2048];
__device__ __align__(16) __half g_dc0[(size_t)B_ROWS * 2048];   // decoder acts
__device__ __align__(16) __half g_dc1[(size_t)B_ROWS * 2048];
__device__ __align__(16) __half g_eh[(size_t)B_ROWS * D_EMB];
__device__ __align__(16) __half g_el[(size_t)B_ROWS * D_EMB];
__device__ __align__(16) __half g_weh[WSUM];
__device__ __align__(16) __half g_wel[WSUM];
__device__ __align__(16) __half g_wd[WSUM];
__device__ __align__(16) __half g_ch[K_CENT * D_EMB];
__device__ __align__(16) __half g_cl[K_CENT * D_EMB];
__device__ __align__(16) float  g_S[(size_t)B_ROWS * K_CENT];
__device__ float g_c2[K_CENT];

// ---------------- helpers ----------------
__device__ __forceinline__ uint32_t smem_u32(const void* p) {
    uint32_t a;
    asm("{ .reg .u64 t; cvta.to.shared.u64 t, %1; cvt.u32.u64 %0, t; }" : "=r"(a) : "l"(p));
    return a;
}
__device__ __forceinline__ void split_fp16(float v, __half& h, __half& l) {
    h = __float2half_rn(v);
    l = __float2half_rn(v - __half2float(h));
}
__device__ __forceinline__ void mma_fp16(float* d, const uint32_t* a, const uint32_t* b) {
    asm volatile(
        "mma.sync.aligned.m16n8k16.row.col.f32.f16.f16.f32 "
        "{%0,%1,%2,%3}, {%4,%5,%6,%7}, {%8,%9}, {%0,%1,%2,%3};"
        : "+f"(d[0]), "+f"(d[1]), "+f"(d[2]), "+f"(d[3])
        : "r"(a[0]), "r"(a[1]), "r"(a[2]), "r"(a[3]), "r"(b[0]), "r"(b[1]));
}
#define LDSM_X4(r0, r1, r2, r3, addr) \
    asm volatile("ldmatrix.sync.aligned.m8n8.x4.shared.b16 {%0,%1,%2,%3}, [%4];" \
                 : "=r"(r0), "=r"(r1), "=r"(r2), "=r"(r3) : "r"(addr))
#define CP16(smaddr, gptr) \
    asm volatile("cp.async.cg.shared.global [%0], [%1], 16;" :: "r"(smaddr), "l"(gptr) : "memory")
#define CP_COMMIT() asm volatile("cp.async.commit_group;" ::: "memory")
#define CP_WAIT(n)  asm volatile("cp.async.wait_group %0;" :: "n"(n) : "memory")

#define SWZ(off) ((off) ^ (((off) >> 3) & 0x70u))

// ===========================================================================
// Encoder GEMM: fp16x3, BK=64, SW128-swizzled smem, 2 stages, 2 CTAs/SM.
// Stage: Ah 16384 | Al 16384 | Bh 8192 | Bl 8192 = 49152 B.
// ===========================================================================
#define FP16E_SMEM (2 * 49152)

__global__ void __launch_bounds__(256, 2)
gemm_fp16e(const __half* __restrict__ Ah, const __half* __restrict__ Al,
           const __half* __restrict__ Bh, const __half* __restrict__ Bl,
           const float* __restrict__ bias,
           float* __restrict__ outF, __half* __restrict__ outH, __half* __restrict__ outL,
           int M, int N, int K, int doRelu)
{
    extern __shared__ __half smh[];
    const int tid  = threadIdx.x;
    const int lane = tid & 31, wid = tid >> 5;
    const int g = lane >> 2, q = lane & 3;
    const int warpM = (wid & 3) * 32, warpN = (wid >> 2) * 32;
    const int brow = blockIdx.y * 128, bcol = blockIdx.x * 64;
    const int nch = K >> 6;
    const uint32_t smb = smem_u32(smh);

    const uint32_t laneRowB = (uint32_t)((lane & 15) * 128);
    const uint32_t laneColC = (uint32_t)((lane >> 4) * 16);
    const uint32_t xorC     = (uint32_t)((lane & 7) * 16);
    uint32_t kcol[4];
    #pragma unroll
    for (int kb = 0; kb < 4; kb++) kcol[kb] = (laneColC + (uint32_t)(kb * 32)) ^ xorC;

    float sum[2][4][4], acc[2][4][4];
    #pragma unroll
    for (int i = 0; i < 2; i++)
        #pragma unroll
        for (int j = 0; j < 4; j++)
            #pragma unroll
            for (int r = 0; r < 4; r++) { sum[i][j][r] = 0.f; acc[i][j][r] = 0.f; }

    const __half* gpA[2] = {Ah, Al};
    const __half* gpB[2] = {Bh, Bl};

    auto issue = [&](int ch, int s) {
        int kt = ch << 6;
        uint32_t sbase = smb + (uint32_t)s * 49152u;
        #pragma unroll
        for (int a = 0; a < 2; a++) {
            uint32_t base = sbase + (uint32_t)a * 16384u;
            #pragma unroll
            for (int it = 0; it < 4; it++) {
                int id = it * 256 + tid;
                uint32_t row = (uint32_t)(id >> 3), seg = (uint32_t)(id & 7);
                uint32_t off = row * 128u + seg * 16u;
                CP16(base + SWZ(off),
                     gpA[a] + (size_t)(brow + (int)row) * K + kt + (int)seg * 8);
            }
        }
        #pragma unroll
        for (int a = 0; a < 2; a++) {
            uint32_t base = sbase + 32768u + (uint32_t)a * 8192u;
            #pragma unroll
            for (int it = 0; it < 2; it++) {
                int id = it * 256 + tid;
                uint32_t row = (uint32_t)(id >> 3), seg = (uint32_t)(id & 7);
                uint32_t off = row * 128u + seg * 16u;
                CP16(base + SWZ(off),
                     gpB[a] + (size_t)(bcol + (int)row) * K + kt + (int)seg * 8);
            }
        }
        CP_COMMIT();
    };

    issue(0, 0);
    if (nch > 1) issue(1, 1);

    for (int c = 0; c < nch; c++) {
        int s = c & 1;
        if (c + 1 < nch) { CP_WAIT(1); } else { CP_WAIT(0); }
        __syncthreads();

        uint32_t sbase = smb + (uint32_t)s * 49152u;
        uint32_t aAh = sbase + (uint32_t)(warpM * 128) + laneRowB;
        uint32_t aAl = aAh + 16384u;
        uint32_t aBh = sbase + 32768u + (uint32_t)(warpN * 128) + laneRowB;
        uint32_t aBl = aBh + 8192u;

        #pragma unroll
        for (int kb = 0; kb < 4; kb++) {
            uint32_t ko = kcol[kb];
            uint32_t ah[2][4], al[2][4];
            #pragma unroll
            for (int i = 0; i < 2; i++) {
                LDSM_X4(ah[i][0], ah[i][1], ah[i][2], ah[i][3], aAh + ko + (uint32_t)(i * 2048));
                LDSM_X4(al[i][0], al[i][1], al[i][2], al[i][3], aAl + ko + (uint32_t)(i * 2048));
            }
            #pragma unroll
            for (int p = 0; p < 2; p++) {
                uint32_t bh4[4], bl4[4];
                LDSM_X4(bh4[0], bh4[1], bh4[2], bh4[3], aBh + ko + (uint32_t)(p * 2048));
                LDSM_X4(bl4[0], bl4[1], bl4[2], bl4[3], aBl + ko + (uint32_t)(p * 2048));
                uint32_t bfh0[2] = {bh4[0], bh4[2]}, bfh1[2] = {bh4[1], bh4[3]};
                uint32_t bfl0[2] = {bl4[0], bl4[2]}, bfl1[2] = {bl4[1], bl4[3]};
                #pragma unroll
                for (int i = 0; i < 2; i++) {
                    mma_fp16(acc[i][p * 2 + 0], ah[i], bfh0);
                    mma_fp16(acc[i][p * 2 + 1], ah[i], bfh1);
                }
                #pragma unroll
                for (int i = 0; i < 2; i++) {
                    mma_fp16(acc[i][p * 2 + 0], ah[i], bfl0);
                    mma_fp16(acc[i][p * 2 + 1], ah[i], bfl1);
                }
                #pragma unroll
                for (int i = 0; i < 2; i++) {
                    mma_fp16(acc[i][p * 2 + 0], al[i], bfh0);
                    mma_fp16(acc[i][p * 2 + 1], al[i], bfh1);
                }
            }
        }

        #pragma unroll
        for (int i = 0; i < 2; i++)
            #pragma unroll
            for (int j = 0; j < 4; j++)
                #pragma unroll
                for (int r = 0; r < 4; r++) {
                    sum[i][j][r] += acc[i][j][r];
                    acc[i][j][r] = 0.f;
                }

        __syncthreads();
        if (c + 2 < nch) issue(c + 2, s);
    }

    #pragma unroll
    for (int i = 0; i < 2; i++) {
        int r0 = brow + warpM + i * 16 + g;
        #pragma unroll
        for (int j = 0; j < 4; j++) {
            int col = bcol + warpN + j * 8 + 2 * q;
            float b0 = 0.f, b1 = 0.f;
            if (bias) { b0 = __ldg(bias + col); b1 = __ldg(bias + col + 1); }
            float v00 = sum[i][j][0] + b0;
            float v01 = sum[i][j][1] + b1;
            float v10 = sum[i][j][2] + b0;
            float v11 = sum[i][j][3] + b1;
            if (doRelu) {
                v00 = fmaxf(v00, 0.f); v01 = fmaxf(v01, 0.f);
                v10 = fmaxf(v10, 0.f); v11 = fmaxf(v11, 0.f);
            }
            size_t o0 = (size_t)r0 * N + col, o1 = o0 + 8 * (size_t)N;
            if (outF) {
                *reinterpret_cast<float2*>(outF + o0) = make_float2(v00, v01);
                *reinterpret_cast<float2*>(outF + o1) = make_float2(v10, v11);
            }
            if (outH) {
                __half h[4], l[4];
                split_fp16(v00, h[0], l[0]); split_fp16(v01, h[1], l[1]);
                split_fp16(v10, h[2], l[2]); split_fp16(v11, h[3], l[3]);
                *reinterpret_cast<__half2*>(outH + o0) = __halves2half2(h[0], h[1]);
                *reinterpret_cast<__half2*>(outH + o1) = __halves2half2(h[2], h[3]);
                *reinterpret_cast<__half2*>(outL + o0) = __halves2half2(l[0], l[1]);
                *reinterpret_cast<__half2*>(outL + o1) = __halves2half2(l[2], l[3]);
            }
        }
    }
}

// ===========================================================================
// Decoder GEMM: fp16x1, BK=64, swizzled smem, 3 stages single-sync, 3 CTAs/SM.
// Stage: A 16384 | W 8192 = 24576 B.
// ===========================================================================
#define FP16S_SMEM (3 * 24576)

__global__ void __launch_bounds__(256, 3)
gemm_fp16s(const __half* __restrict__ A, const __half* __restrict__ W,
           const float* __restrict__ bias,
           float* __restrict__ outF, __half* __restrict__ outH,
           int M, int N, int K, int doRelu)
{
    extern __shared__ __half smh[];
    const int tid  = threadIdx.x;
    const int lane = tid & 31, wid = tid >> 5;
    const int g = lane >> 2, q = lane & 3;
    const int warpM = (wid & 3) * 32, warpN = (wid >> 2) * 32;
    const int brow = blockIdx.y * 128, bcol = blockIdx.x * 64;
    const int nch = K >> 6;
    const uint32_t smb = smem_u32(smh);

    const uint32_t laneRowB = (uint32_t)((lane & 15) * 128);
    const uint32_t laneColC = (uint32_t)((lane >> 4) * 16);
    const uint32_t xorC     = (uint32_t)((lane & 7) * 16);
    uint32_t kcol[4];
    #pragma unroll
    for (int kb = 0; kb < 4; kb++) kcol[kb] = (laneColC + (uint32_t)(kb * 32)) ^ xorC;

    float acc[2][4][4];
    #pragma unroll
    for (int i = 0; i < 2; i++)
        #pragma unroll
        for (int j = 0; j < 4; j++)
            #pragma unroll
            for (int r = 0; r < 4; r++) acc[i][j][r] = 0.f;

    auto issue = [&](int ch, int s) {
        int kt = ch << 6;
        uint32_t sbase = smb + (uint32_t)s * 24576u;
        #pragma unroll
        for (int it = 0; it < 4; it++) {
            int id = it * 256 + tid;
            uint32_t row = (uint32_t)(id >> 3), seg = (uint32_t)(id & 7);
            uint32_t off = row * 128u + seg * 16u;
            CP16(sbase + SWZ(off),
                 A + (size_t)(brow + (int)row) * K + kt + (int)seg * 8);
        }
        {
            uint32_t base = sbase + 16384u;
            #pragma unroll
            for (int it = 0; it < 2; it++) {
                int id = it * 256 + tid;
                uint32_t row = (uint32_t)(id >> 3), seg = (uint32_t)(id & 7);
                uint32_t off = row * 128u + seg * 16u;
                CP16(base + SWZ(off),
                     W + (size_t)(bcol + (int)row) * K + kt + (int)seg * 8);
            }
        }
        CP_COMMIT();
    };

    issue(0, 0);
    if (nch > 1) issue(1, 1);

    for (int c = 0; c < nch; c++) {
        int s = c % 3;
        if (c + 1 < nch) { CP_WAIT(1); } else { CP_WAIT(0); }
        __syncthreads();
        if (c + 2 < nch) issue(c + 2, (c + 2) % 3);

        uint32_t sbase = smb + (uint32_t)s * 24576u;
        uint32_t aA = sbase + (uint32_t)(warpM * 128) + laneRowB;
        uint32_t aW = sbase + 16384u + (uint32_t)(warpN * 128) + laneRowB;

        #pragma unroll
        for (int kb = 0; kb < 4; kb++) {
            uint32_t ko = kcol[kb];
            uint32_t a4[2][4];
            #pragma unroll
            for (int i = 0; i < 2; i++)
                LDSM_X4(a4[i][0], a4[i][1], a4[i][2], a4[i][3], aA + ko + (uint32_t)(i * 2048));
            #pragma unroll
            for (int p = 0; p < 2; p++) {
                uint32_t w4[4];
                LDSM_X4(w4[0], w4[1], w4[2], w4[3], aW + ko + (uint32_t)(p * 2048));
                uint32_t bf0[2] = {w4[0], w4[2]}, bf1[2] = {w4[1], w4[3]};
                #pragma unroll
                for (int i = 0; i < 2; i++) {
                    mma_fp16(acc[i][p * 2 + 0], a4[i], bf0);
                    mma_fp16(acc[i][p * 2 + 1], a4[i], bf1);
                }
            }
        }
    }

    #pragma unroll
    for (int i = 0; i < 2; i++) {
        int r0 = brow + warpM + i * 16 + g;
        #pragma unroll
        for (int j = 0; j < 4; j++) {
            int col = bcol + warpN + j * 8 + 2 * q;
            float b0 = 0.f, b1 = 0.f;
            if (bias) { b0 = __ldg(bias + col); b1 = __ldg(bias + col + 1); }
            float v00 = acc[i][j][0] + b0, v01 = acc[i][j][1] + b1;
            float v10 = acc[i][j][2] + b0, v11 = acc[i][j][3] + b1;
            if (doRelu) {
                v00 = fmaxf(v00, 0.f); v01 = fmaxf(v01, 0.f);
                v10 = fmaxf(v10, 0.f); v11 = fmaxf(v11, 0.f);
            }
            size_t o0 = (size_t)r0 * N + col, o1 = o0 + 8 * (size_t)N;
            if (outF) {
                *reinterpret_cast<float2*>(outF + o0) = make_float2(v00, v01);
                *reinterpret_cast<float2*>(outF + o1) = make_float2(v10, v11);
            }
            if (outH) {
                *reinterpret_cast<__half2*>(outH + o0) =
                    __halves2half2(__float2half_rn(v00), __float2half_rn(v01));
                *reinterpret_cast<__half2*>(outH + o1) =
                    __halves2half2(__float2half_rn(v10), __float2half_rn(v11));
            }
        }
    }
}

// ---------------- prep kernels ----------------
__global__ void vec_split_fp16(const float* __restrict__ a,
                               __half* __restrict__ hi, __half* __restrict__ lo, int n2)
{
    int i = blockIdx.x * blockDim.x + threadIdx.x;
    if (i >= n2) return;
    float2 v = reinterpret_cast<const float2*>(a)[i];
    __half hx, lx, hy, ly;
    split_fp16(v.x, hx, lx); split_fp16(v.y, hy, ly);
    reinterpret_cast<__half2*>(hi)[i] = __halves2half2(hx, hy);
    reinterpret_cast<__half2*>(lo)[i] = __halves2half2(lx, ly);
}

__global__ void wt_split_fp16(const float* __restrict__ W, __half* __restrict__ hi,
                              __half* __restrict__ lo, int Kd, int N)
{
    __shared__ float t[32][33];
    int bx = blockIdx.x * 32, by = blockIdx.y * 32;
    for (int i = threadIdx.y; i < 32; i += 8)
        t[i][threadIdx.x] = W[(size_t)(by + i) * N + bx + threadIdx.x];
    __syncthreads();
    for (int i = threadIdx.y; i < 32; i += 8) {
        float v = t[threadIdx.x][i];
        __half h, l;
        split_fp16(v, h, l);
        size_t o = (size_t)(bx + i) * Kd + by + threadIdx.x;
        hi[o] = h; lo[o] = l;
    }
}

__global__ void wt_single_fp16(const float* __restrict__ W, __half* __restrict__ out,
                               int Kd, int N)
{
    __shared__ float t[32][33];
    int bx = blockIdx.x * 32, by = blockIdx.y * 32;
    for (int i = threadIdx.y; i < 32; i += 8)
        t[i][threadIdx.x] = W[(size_t)(by + i) * N + bx + threadIdx.x];
    __syncthreads();
    for (int i = threadIdx.y; i < 32; i += 8)
        out[(size_t)(bx + i) * Kd + by + threadIdx.x] = __float2half_rn(t[threadIdx.x][i]);
}

__global__ void c2_kernel(const float* __restrict__ c, float* __restrict__ c2)
{
    int k = blockIdx.x * 8 + (threadIdx.x >> 5);
    int lane = threadIdx.x & 31;
    float s = 0.0f;
    for (int d = lane; d < D_EMB; d += 32) {
        float v = c[(size_t)k * D_EMB + d];
        s = fmaf(v, v, s);
    }
    #pragma unroll
    for (int o = 16; o; o >>= 1) s += __shfl_xor_sync(0xFFFFFFFFu, s, o);
    if (lane == 0) c2[k] = s;
}

__global__ void argmin_labels(const float* __restrict__ emb, const float* __restrict__ S,
                              const float* __restrict__ c2, float* __restrict__ labels)
{
    const int row = blockIdx.x, tid = threadIdx.x;
    __shared__ float red[256];
    float v = emb[(size_t)row * D_EMB + tid];
    red[tid] = v * v;
    __syncthreads();
    #pragma unroll
    for (int s = 128; s > 0; s >>= 1) {
        if (tid < s) red[tid] += red[tid + s];
        __syncthreads();
    }
    const float e2 = red[0];
    __syncthreads();
    float best = 3.402823466e38f;
    int bi = 0;
    for (int k = tid; k < K_CENT; k += 256) {
        float d = fmaxf(e2 + c2[k] - 2.0f * S[(size_t)row * K_CENT + k], 0.0f);
        if (d < best) { best = d; bi = k; }
    }
    __shared__ float sv[256];
    __shared__ int si[256];
    sv[tid] = best; si[tid] = bi;
    __syncthreads();
    #pragma unroll
    for (int s = 128; s > 0; s >>= 1) {
        if (tid < s) {
            float v2 = sv[tid + s]; int i2 = si[tid + s];
            if (v2 < sv[tid] || (v2 == sv[tid] && i2 < si[tid])) { sv[tid] = v2; si[tid] = i2; }
        }
        __syncthreads();
    }
    const int win = si[0];
    for (int k = tid; k < K_CENT; k += 256)
        labels[(size_t)row * K_CENT + k] = (k == win) ? 1.0f : 0.0f;
}

// ---------------- host launcher ----------------
extern "C" void kernel_launch(void* const* d_in, const int* in_sizes, int n_in,
                              void* d_out, int out_size)
{
    (void)in_sizes; (void)n_in; (void)out_size;

    static cudaStream_t sB = nullptr;
    static cudaEvent_t evFork = nullptr, evPrep = nullptr, evEmb = nullptr, evJoin = nullptr;
    if (!sB) {
        cudaStreamCreateWithFlags(&sB, cudaStreamNonBlocking);
        cudaEventCreateWithFlags(&evFork, cudaEventDisableTiming);
        cudaEventCreateWithFlags(&evPrep, cudaEventDisableTiming);
        cudaEventCreateWithFlags(&evEmb,  cudaEventDisableTiming);
        cudaEventCreateWithFlags(&evJoin, cudaEventDisableTiming);
    }

    cudaFuncSetAttribute(gemm_fp16e, cudaFuncAttributeMaxDynamicSharedMemorySize, FP16E_SMEM);
    cudaFuncSetAttribute(gemm_fp16s, cudaFuncAttributeMaxDynamicSharedMemorySize, FP16S_SMEM);

    const float* x = (const float*)d_in[0];
    const float* W[8]  = {(const float*)d_in[1],  (const float*)d_in[3],
                          (const float*)d_in[5],  (const float*)d_in[7],
                          (const float*)d_in[9],  (const float*)d_in[11],
                          (const float*)d_in[13], (const float*)d_in[15]};
    const float* bv[8] = {(const float*)d_in[2],  (const float*)d_in[4],
                          (const float*)d_in[6],  (const float*)d_in[8],
                          (const float*)d_in[10], (const float*)d_in[12],
                          (const float*)d_in[14], (const float*)d_in[16]};
    const float* centers = (const float*)d_in[17];

    float* out    = (float*)d_out;
    float* recon  = out;
    float* emb    = out + (size_t)B_ROWS * D_IN;
    float* labels = emb + (size_t)B_ROWS * D_EMB;

    __half *xh, *xl, *h0h, *h0l, *h1h, *h1l, *dc0, *dc1, *eh, *el, *weh, *wel, *wd, *ch, *cl;
    float *S, *c2;
    cudaGetSymbolAddress((void**)&xh, g_xh);   cudaGetSymbolAddress((void**)&xl, g_xl);
    cudaGetSymbolAddress((void**)&h0h, g_h0h); cudaGetSymbolAddress((void**)&h0l, g_h0l);
    cudaGetSymbolAddress((void**)&h1h, g_h1h); cudaGetSymbolAddress((void**)&h1l, g_h1l);
    cudaGetSymbolAddress((void**)&dc0, g_dc0); cudaGetSymbolAddress((void**)&dc1, g_dc1);
    cudaGetSymbolAddress((void**)&eh, g_eh);   cudaGetSymbolAddress((void**)&el, g_el);
    cudaGetSymbolAddress((void**)&weh, g_weh); cudaGetSymbolAddress((void**)&wel, g_wel);
    cudaGetSymbolAddress((void**)&wd, g_wd);
    cudaGetSymbolAddress((void**)&ch, g_ch);   cudaGetSymbolAddress((void**)&cl, g_cl);
    cudaGetSymbolAddress((void**)&S, g_S);     cudaGetSymbolAddress((void**)&c2, g_c2);

    const int fi[8] = {1024, 2048, 1024, 512, 256, 512, 1024, 2048};
    const int fo[8] = {2048, 1024, 512, 256, 512, 1024, 2048, 1024};
    size_t off[8], acc = 0, accd = 0;
    for (int i = 0; i < 4; i++) { off[i] = acc;  acc  += (size_t)fi[i] * fo[i]; }
    for (int i = 4; i < 8; i++) { off[i] = accd; accd += (size_t)fi[i] * fo[i]; }

    // ---- fork side stream (emb-independent prep) ----
    cudaEventRecord(evFork, 0);
    cudaStreamWaitEvent(sB, evFork, 0);
    c2_kernel<<<K_CENT / 8, 256, 0, sB>>>(centers, c2);
    vec_split_fp16<<<(K_CENT * D_EMB / 2 + 255) / 256, 256, 0, sB>>>(
        centers, ch, cl, K_CENT * D_EMB / 2);
    for (int i = 4; i < 8; i++) {
        dim3 g(fo[i] / 32, fi[i] / 32), b(32, 8);
        wt_single_fp16<<<g, b, 0, sB>>>(W[i], wd + off[i], fi[i], fo[i]);
    }
    cudaEventRecord(evPrep, sB);

    // ---- main stream: encoder ----
    vec_split_fp16<<<(B_ROWS * D_IN / 2 + 255) / 256, 256>>>(x, xh, xl, B_ROWS * D_IN / 2);
    for (int i = 0; i < 4; i++) {
        dim3 g(fo[i] / 32, fi[i] / 32), b(32, 8);
        wt_split_fp16<<<g, b>>>(W[i], weh + off[i], wel + off[i], fi[i], fo[i]);
    }
    {
        dim3 g0(2048 / 64, B_ROWS / 128);
        gemm_fp16e<<<g0, 256, FP16E_SMEM>>>(xh, xl, weh + off[0], wel + off[0], bv[0],
                                            nullptr, h0h, h0l, B_ROWS, 2048, 1024, 1);
        dim3 g1(1024 / 64, B_ROWS / 128);
        gemm_fp16e<<<g1, 256, FP16E_SMEM>>>(h0h, h0l, weh + off[1], wel + off[1], bv[1],
                                            nullptr, h1h, h1l, B_ROWS, 1024, 2048, 1);
        dim3 g2(512 / 64, B_ROWS / 128);
        gemm_fp16e<<<g2, 256, FP16E_SMEM>>>(h1h, h1l, weh + off[2], wel + off[2], bv[2],
                                            nullptr, h0h, h0l, B_ROWS, 512, 1024, 1);
        dim3 g3(256 / 64, B_ROWS / 128);
        gemm_fp16e<<<g3, 256, FP16E_SMEM>>>(h0h, h0l, weh + off[3], wel + off[3], bv[3],
                                            emb, eh, el, B_ROWS, 256, 512, 0);
    }
    cudaEventRecord(evEmb, 0);

    // ---- side stream: decoder chain (waits for emb + its own prep) ----
    cudaStreamWaitEvent(sB, evEmb, 0);
    {
        dim3 g0(512 / 64, B_ROWS / 128);
        gemm_fp16s<<<g0, 256, FP16S_SMEM, sB>>>(eh, wd + off[4], bv[4],
                                                nullptr, dc0, B_ROWS, 512, 256, 1);
        dim3 g1(1024 / 64, B_ROWS / 128);
        gemm_fp16s<<<g1, 256, FP16S_SMEM, sB>>>(dc0, wd + off[5], bv[5],
                                                nullptr, dc1, B_ROWS, 1024, 512, 1);
        dim3 g2(2048 / 64, B_ROWS / 128);
        gemm_fp16s<<<g2, 256, FP16S_SMEM, sB>>>(dc1, wd + off[6], bv[6],
                                                nullptr, dc0, B_ROWS, 2048, 1024, 1);
        dim3 g3(1024 / 64, B_ROWS / 128);
        gemm_fp16s<<<g3, 256, FP16S_SMEM, sB>>>(dc0, wd + off[7], bv[7],
                                                recon, nullptr, B_ROWS, 1024, 2048, 0);
    }
    cudaEventRecord(evJoin, sB);

    // ---- main stream: clustering (needs ch/cl from side prep) ----
    cudaStreamWaitEvent(0, evPrep, 0);
    {
        dim3 g(K_CENT / 64, B_ROWS / 128);
        gemm_fp16e<<<g, 256, FP16E_SMEM>>>(eh, el, ch, cl, nullptr,
                                           S, nullptr, nullptr, B_ROWS, K_CENT, D_EMB, 0);
    }
    argmin_labels<<<B_ROWS, 256>>>(emb, S, c2, labels);

    // ---- join decoder ----
    cudaStreamWaitEvent(0, evJoin, 0);
}

// round 16
// speedup vs baseline: 1.8958x; 1.0438x over previous
#include <cuda_runtime.h>
#include <cuda_fp16.h>
#include <cstdint>
#include <cstddef>

#define B_ROWS 8192
#define D_IN   1024
#define D_EMB  256
#define K_CENT 1024
#define WSUM   4849664

// ---------------- device scratch ----------------
__device__ __align__(16) __half g_xh[(size_t)B_ROWS * D_IN];
__device__ __align__(16) __half g_xl[(size_t)B_ROWS * D_IN];
__device__ __align__(16) __half g_h0h[(size_t)B_ROWS * 2048];
__device__ __align__(16) __half g_h0l[(size_t)B_ROWS * 2048];
__device__ __align__(16) __half g_h1h[(size_t)B_ROWS * 2048];
__device__ __align__(16) __half g_h1l[(size_t)B_ROWS * 2048];
__device__ __align__(16) __half g_dc0[(size_t)B_ROWS * 2048];
__device__ __align__(16) __half g_dc1[(size_t)B_ROWS * 2048];
__device__ __align__(16) __half g_eh[(size_t)B_ROWS * D_EMB];
__device__ __align__(16) __half g_el[(size_t)B_ROWS * D_EMB];
__device__ __align__(16) __half g_weh[WSUM];
__device__ __align__(16) __half g_wel[WSUM];
__device__ __align__(16) __half g_wd[WSUM];
__device__ __align__(16) __half g_ch[K_CENT * D_EMB];
__device__ __align__(16) __half g_cl[K_CENT * D_EMB];
__device__ float g_c2[K_CENT];
__device__ float g_e2[B_ROWS];
__device__ unsigned long long g_best[B_ROWS];

// ---------------- helpers ----------------
__device__ __forceinline__ uint32_t smem_u32(const void* p) {
    uint32_t a;
    asm("{ .reg .u64 t; cvta.to.shared.u64 t, %1; cvt.u32.u64 %0, t; }" : "=r"(a) : "l"(p));
    return a;
}
__device__ __forceinline__ void split_fp16(float v, __half& h, __half& l) {
    h = __float2half_rn(v);
    l = __float2half_rn(v - __half2float(h));
}
__device__ __forceinline__ void mma_fp16(float* d, const uint32_t* a, const uint32_t* b) {
    asm volatile(
        "mma.sync.aligned.m16n8k16.row.col.f32.f16.f16.f32 "
        "{%0,%1,%2,%3}, {%4,%5,%6,%7}, {%8,%9}, {%0,%1,%2,%3};"
        : "+f"(d[0]), "+f"(d[1]), "+f"(d[2]), "+f"(d[3])
        : "r"(a[0]), "r"(a[1]), "r"(a[2]), "r"(a[3]), "r"(b[0]), "r"(b[1]));
}
#define LDSM_X4(r0, r1, r2, r3, addr) \
    asm volatile("ldmatrix.sync.aligned.m8n8.x4.shared.b16 {%0,%1,%2,%3}, [%4];" \
                 : "=r"(r0), "=r"(r1), "=r"(r2), "=r"(r3) : "r"(addr))
#define CP16(smaddr, gptr) \
    asm volatile("cp.async.cg.shared.global [%0], [%1], 16;" :: "r"(smaddr), "l"(gptr) : "memory")
#define CP_COMMIT() asm volatile("cp.async.commit_group;" ::: "memory")
#define CP_WAIT(n)  asm volatile("cp.async.wait_group %0;" :: "n"(n) : "memory")

#define SWZ(off) ((off) ^ (((off) >> 3) & 0x70u))

__device__ __forceinline__ unsigned long long pack_di(float d, int idx) {
    return ((unsigned long long)__float_as_uint(d) << 32) | (unsigned int)idx;
}

// ===========================================================================
// Encoder GEMM: fp16x3, BK=64, SW128-swizzled smem, 2 stages, 2 CTAs/SM.
// Epilogue modes: fp32 out / fp16 split pair out / fused cdist-argmin (best).
// ===========================================================================
#define FP16E_SMEM (2 * 49152)

__global__ void __launch_bounds__(256, 2)
gemm_fp16e(const __half* __restrict__ Ah, const __half* __restrict__ Al,
           const __half* __restrict__ Bh, const __half* __restrict__ Bl,
           const float* __restrict__ bias,
           float* __restrict__ outF, __half* __restrict__ outH, __half* __restrict__ outL,
           const float* __restrict__ e2v, const float* __restrict__ c2v,
           unsigned long long* __restrict__ best,
           int M, int N, int K, int doRelu)
{
    extern __shared__ __half smh[];
    const int tid  = threadIdx.x;
    const int lane = tid & 31, wid = tid >> 5;
    const int g = lane >> 2, q = lane & 3;
    const int warpM = (wid & 3) * 32, warpN = (wid >> 2) * 32;
    const int brow = blockIdx.y * 128, bcol = blockIdx.x * 64;
    const int nch = K >> 6;
    const uint32_t smb = smem_u32(smh);

    const uint32_t laneRowB = (uint32_t)((lane & 15) * 128);
    const uint32_t laneColC = (uint32_t)((lane >> 4) * 16);
    const uint32_t xorC     = (uint32_t)((lane & 7) * 16);
    uint32_t kcol[4];
    #pragma unroll
    for (int kb = 0; kb < 4; kb++) kcol[kb] = (laneColC + (uint32_t)(kb * 32)) ^ xorC;

    float sum[2][4][4], acc[2][4][4];
    #pragma unroll
    for (int i = 0; i < 2; i++)
        #pragma unroll
        for (int j = 0; j < 4; j++)
            #pragma unroll
            for (int r = 0; r < 4; r++) { sum[i][j][r] = 0.f; acc[i][j][r] = 0.f; }

    const __half* gpA[2] = {Ah, Al};
    const __half* gpB[2] = {Bh, Bl};

    auto issue = [&](int ch, int s) {
        int kt = ch << 6;
        uint32_t sbase = smb + (uint32_t)s * 49152u;
        #pragma unroll
        for (int a = 0; a < 2; a++) {
            uint32_t base = sbase + (uint32_t)a * 16384u;
            #pragma unroll
            for (int it = 0; it < 4; it++) {
                int id = it * 256 + tid;
                uint32_t row = (uint32_t)(id >> 3), seg = (uint32_t)(id & 7);
                uint32_t off = row * 128u + seg * 16u;
                CP16(base + SWZ(off),
                     gpA[a] + (size_t)(brow + (int)row) * K + kt + (int)seg * 8);
            }
        }
        #pragma unroll
        for (int a = 0; a < 2; a++) {
            uint32_t base = sbase + 32768u + (uint32_t)a * 8192u;
            #pragma unroll
            for (int it = 0; it < 2; it++) {
                int id = it * 256 + tid;
                uint32_t row = (uint32_t)(id >> 3), seg = (uint32_t)(id & 7);
                uint32_t off = row * 128u + seg * 16u;
                CP16(base + SWZ(off),
                     gpB[a] + (size_t)(bcol + (int)row) * K + kt + (int)seg * 8);
            }
        }
        CP_COMMIT();
    };

    issue(0, 0);
    if (nch > 1) issue(1, 1);

    for (int c = 0; c < nch; c++) {
        int s = c & 1;
        if (c + 1 < nch) { CP_WAIT(1); } else { CP_WAIT(0); }
        __syncthreads();

        uint32_t sbase = smb + (uint32_t)s * 49152u;
        uint32_t aAh = sbase + (uint32_t)(warpM * 128) + laneRowB;
        uint32_t aAl = aAh + 16384u;
        uint32_t aBh = sbase + 32768u + (uint32_t)(warpN * 128) + laneRowB;
        uint32_t aBl = aBh + 8192u;

        #pragma unroll
        for (int kb = 0; kb < 4; kb++) {
            uint32_t ko = kcol[kb];
            uint32_t ah[2][4], al[2][4];
            #pragma unroll
            for (int i = 0; i < 2; i++) {
                LDSM_X4(ah[i][0], ah[i][1], ah[i][2], ah[i][3], aAh + ko + (uint32_t)(i * 2048));
                LDSM_X4(al[i][0], al[i][1], al[i][2], al[i][3], aAl + ko + (uint32_t)(i * 2048));
            }
            #pragma unroll
            for (int p = 0; p < 2; p++) {
                uint32_t bh4[4], bl4[4];
                LDSM_X4(bh4[0], bh4[1], bh4[2], bh4[3], aBh + ko + (uint32_t)(p * 2048));
                LDSM_X4(bl4[0], bl4[1], bl4[2], bl4[3], aBl + ko + (uint32_t)(p * 2048));
                uint32_t bfh0[2] = {bh4[0], bh4[2]}, bfh1[2] = {bh4[1], bh4[3]};
                uint32_t bfl0[2] = {bl4[0], bl4[2]}, bfl1[2] = {bl4[1], bl4[3]};
                #pragma unroll
                for (int i = 0; i < 2; i++) {
                    mma_fp16(acc[i][p * 2 + 0], ah[i], bfh0);
                    mma_fp16(acc[i][p * 2 + 1], ah[i], bfh1);
                }
                #pragma unroll
                for (int i = 0; i < 2; i++) {
                    mma_fp16(acc[i][p * 2 + 0], ah[i], bfl0);
                    mma_fp16(acc[i][p * 2 + 1], ah[i], bfl1);
                }
                #pragma unroll
                for (int i = 0; i < 2; i++) {
                    mma_fp16(acc[i][p * 2 + 0], al[i], bfh0);
                    mma_fp16(acc[i][p * 2 + 1], al[i], bfh1);
                }
            }
        }

        #pragma unroll
        for (int i = 0; i < 2; i++)
            #pragma unroll
            for (int j = 0; j < 4; j++)
                #pragma unroll
                for (int r = 0; r < 4; r++) {
                    sum[i][j][r] += acc[i][j][r];
                    acc[i][j][r] = 0.f;
                }

        __syncthreads();
        if (c + 2 < nch) issue(c + 2, s);
    }

    if (best) {
        // fused cdist argmin: d = max(e2[row] + c2[col] - 2*s, 0)
        #pragma unroll
        for (int i = 0; i < 2; i++) {
            #pragma unroll
            for (int rr = 0; rr < 2; rr++) {      // rr=0 -> row r0, rr=1 -> r0+8
                int row = brow + warpM + i * 16 + g + rr * 8;
                float e2 = __ldg(e2v + row);
                unsigned long long bloc = 0xFFFFFFFFFFFFFFFFull;
                #pragma unroll
                for (int j = 0; j < 4; j++) {
                    int col = bcol + warpN + j * 8 + 2 * q;
                    float c20 = __ldg(c2v + col);
                    float c21 = __ldg(c2v + col + 1);
                    float d0 = fmaxf(e2 + c20 - 2.0f * sum[i][j][rr * 2 + 0], 0.0f);
                    float d1 = fmaxf(e2 + c21 - 2.0f * sum[i][j][rr * 2 + 1], 0.0f);
                    unsigned long long p0 = pack_di(d0, col);
                    unsigned long long p1 = pack_di(d1, col + 1);
                    if (p0 < bloc) bloc = p0;
                    if (p1 < bloc) bloc = p1;
                }
                atomicMin(best + row, bloc);
            }
        }
        return;
    }

    #pragma unroll
    for (int i = 0; i < 2; i++) {
        int r0 = brow + warpM + i * 16 + g;
        #pragma unroll
        for (int j = 0; j < 4; j++) {
            int col = bcol + warpN + j * 8 + 2 * q;
            float b0 = 0.f, b1 = 0.f;
            if (bias) { b0 = __ldg(bias + col); b1 = __ldg(bias + col + 1); }
            float v00 = sum[i][j][0] + b0;
            float v01 = sum[i][j][1] + b1;
            float v10 = sum[i][j][2] + b0;
            float v11 = sum[i][j][3] + b1;
            if (doRelu) {
                v00 = fmaxf(v00, 0.f); v01 = fmaxf(v01, 0.f);
                v10 = fmaxf(v10, 0.f); v11 = fmaxf(v11, 0.f);
            }
            size_t o0 = (size_t)r0 * N + col, o1 = o0 + 8 * (size_t)N;
            if (outF) {
                *reinterpret_cast<float2*>(outF + o0) = make_float2(v00, v01);
                *reinterpret_cast<float2*>(outF + o1) = make_float2(v10, v11);
            }
            if (outH) {
                __half h[4], l[4];
                split_fp16(v00, h[0], l[0]); split_fp16(v01, h[1], l[1]);
                split_fp16(v10, h[2], l[2]); split_fp16(v11, h[3], l[3]);
                *reinterpret_cast<__half2*>(outH + o0) = __halves2half2(h[0], h[1]);
                *reinterpret_cast<__half2*>(outH + o1) = __halves2half2(h[2], h[3]);
                *reinterpret_cast<__half2*>(outL + o0) = __halves2half2(l[0], l[1]);
                *reinterpret_cast<__half2*>(outL + o1) = __halves2half2(l[2], l[3]);
            }
        }
    }
}

// ===========================================================================
// Decoder GEMM: fp16x1, BK=64, swizzled, 3 stages single-sync, 3 CTAs/SM.
// ===========================================================================
#define FP16S_SMEM (3 * 24576)

__global__ void __launch_bounds__(256, 3)
gemm_fp16s(const __half* __restrict__ A, const __half* __restrict__ W,
           const float* __restrict__ bias,
           float* __restrict__ outF, __half* __restrict__ outH,
           int M, int N, int K, int doRelu)
{
    extern __shared__ __half smh[];
    const int tid  = threadIdx.x;
    const int lane = tid & 31, wid = tid >> 5;
    const int g = lane >> 2, q = lane & 3;
    const int warpM = (wid & 3) * 32, warpN = (wid >> 2) * 32;
    const int brow = blockIdx.y * 128, bcol = blockIdx.x * 64;
    const int nch = K >> 6;
    const uint32_t smb = smem_u32(smh);

    const uint32_t laneRowB = (uint32_t)((lane & 15) * 128);
    const uint32_t laneColC = (uint32_t)((lane >> 4) * 16);
    const uint32_t xorC     = (uint32_t)((lane & 7) * 16);
    uint32_t kcol[4];
    #pragma unroll
    for (int kb = 0; kb < 4; kb++) kcol[kb] = (laneColC + (uint32_t)(kb * 32)) ^ xorC;

    float acc[2][4][4];
    #pragma unroll
    for (int i = 0; i < 2; i++)
        #pragma unroll
        for (int j = 0; j < 4; j++)
            #pragma unroll
            for (int r = 0; r < 4; r++) acc[i][j][r] = 0.f;

    auto issue = [&](int ch, int s) {
        int kt = ch << 6;
        uint32_t sbase = smb + (uint32_t)s * 24576u;
        #pragma unroll
        for (int it = 0; it < 4; it++) {
            int id = it * 256 + tid;
            uint32_t row = (uint32_t)(id >> 3), seg = (uint32_t)(id & 7);
            uint32_t off = row * 128u + seg * 16u;
            CP16(sbase + SWZ(off),
                 A + (size_t)(brow + (int)row) * K + kt + (int)seg * 8);
        }
        {
            uint32_t base = sbase + 16384u;
            #pragma unroll
            for (int it = 0; it < 2; it++) {
                int id = it * 256 + tid;
                uint32_t row = (uint32_t)(id >> 3), seg = (uint32_t)(id & 7);
                uint32_t off = row * 128u + seg * 16u;
                CP16(base + SWZ(off),
                     W + (size_t)(bcol + (int)row) * K + kt + (int)seg * 8);
            }
        }
        CP_COMMIT();
    };

    issue(0, 0);
    if (nch > 1) issue(1, 1);

    for (int c = 0; c < nch; c++) {
        int s = c % 3;
        if (c + 1 < nch) { CP_WAIT(1); } else { CP_WAIT(0); }
        __syncthreads();
        if (c + 2 < nch) issue(c + 2, (c + 2) % 3);

        uint32_t sbase = smb + (uint32_t)s * 24576u;
        uint32_t aA = sbase + (uint32_t)(warpM * 128) + laneRowB;
        uint32_t aW = sbase + 16384u + (uint32_t)(warpN * 128) + laneRowB;

        #pragma unroll
        for (int kb = 0; kb < 4; kb++) {
            uint32_t ko = kcol[kb];
            uint32_t a4[2][4];
            #pragma unroll
            for (int i = 0; i < 2; i++)
                LDSM_X4(a4[i][0], a4[i][1], a4[i][2], a4[i][3], aA + ko + (uint32_t)(i * 2048));
            #pragma unroll
            for (int p = 0; p < 2; p++) {
                uint32_t w4[4];
                LDSM_X4(w4[0], w4[1], w4[2], w4[3], aW + ko + (uint32_t)(p * 2048));
                uint32_t bf0[2] = {w4[0], w4[2]}, bf1[2] = {w4[1], w4[3]};
                #pragma unroll
                for (int i = 0; i < 2; i++) {
                    mma_fp16(acc[i][p * 2 + 0], a4[i], bf0);
                    mma_fp16(acc[i][p * 2 + 1], a4[i], bf1);
                }
            }
        }
    }

    #pragma unroll
    for (int i = 0; i < 2; i++) {
        int r0 = brow + warpM + i * 16 + g;
        #pragma unroll
        for (int j = 0; j < 4; j++) {
            int col = bcol + warpN + j * 8 + 2 * q;
            float b0 = 0.f, b1 = 0.f;
            if (bias) { b0 = __ldg(bias + col); b1 = __ldg(bias + col + 1); }
            float v00 = acc[i][j][0] + b0, v01 = acc[i][j][1] + b1;
            float v10 = acc[i][j][2] + b0, v11 = acc[i][j][3] + b1;
            if (doRelu) {
                v00 = fmaxf(v00, 0.f); v01 = fmaxf(v01, 0.f);
                v10 = fmaxf(v10, 0.f); v11 = fmaxf(v11, 0.f);
            }
            size_t o0 = (size_t)r0 * N + col, o1 = o0 + 8 * (size_t)N;
            if (outF) {
                *reinterpret_cast<float2*>(outF + o0) = make_float2(v00, v01);
                *reinterpret_cast<float2*>(outF + o1) = make_float2(v10, v11);
            }
            if (outH) {
                *reinterpret_cast<__half2*>(outH + o0) =
                    __halves2half2(__float2half_rn(v00), __float2half_rn(v01));
                *reinterpret_cast<__half2*>(outH + o1) =
                    __halves2half2(__float2half_rn(v10), __float2half_rn(v11));
            }
        }
    }
}

// ---------------- prep / small kernels ----------------
__global__ void vec_split_fp16(const float* __restrict__ a,
                               __half* __restrict__ hi, __half* __restrict__ lo, int n2)
{
    int i = blockIdx.x * blockDim.x + threadIdx.x;
    if (i >= n2) return;
    float2 v = reinterpret_cast<const float2*>(a)[i];
    __half hx, lx, hy, ly;
    split_fp16(v.x, hx, lx); split_fp16(v.y, hy, ly);
    reinterpret_cast<__half2*>(hi)[i] = __halves2half2(hx, hy);
    reinterpret_cast<__half2*>(lo)[i] = __halves2half2(lx, ly);
}

__global__ void wt_split_fp16(const float* __restrict__ W, __half* __restrict__ hi,
                              __half* __restrict__ lo, int Kd, int N)
{
    __shared__ float t[32][33];
    int bx = blockIdx.x * 32, by = blockIdx.y * 32;
    for (int i = threadIdx.y; i < 32; i += 8)
        t[i][threadIdx.x] = W[(size_t)(by + i) * N + bx + threadIdx.x];
    __syncthreads();
    for (int i = threadIdx.y; i < 32; i += 8) {
        float v = t[threadIdx.x][i];
        __half h, l;
        split_fp16(v, h, l);
        size_t o = (size_t)(bx + i) * Kd + by + threadIdx.x;
        hi[o] = h; lo[o] = l;
    }
}

__global__ void wt_single_fp16(const float* __restrict__ W, __half* __restrict__ out,
                               int Kd, int N)
{
    __shared__ float t[32][33];
    int bx = blockIdx.x * 32, by = blockIdx.y * 32;
    for (int i = threadIdx.y; i < 32; i += 8)
        t[i][threadIdx.x] = W[(size_t)(by + i) * N + bx + threadIdx.x];
    __syncthreads();
    for (int i = threadIdx.y; i < 32; i += 8)
        out[(size_t)(bx + i) * Kd + by + threadIdx.x] = __float2half_rn(t[threadIdx.x][i]);
}

__global__ void rowsq_kernel(const float* __restrict__ a, float* __restrict__ out, int D)
{   // out[r] = sum_d a[r][d]^2 ; one warp per row
    int r = blockIdx.x * 8 + (threadIdx.x >> 5);
    int lane = threadIdx.x & 31;
    float s = 0.0f;
    for (int d = lane; d < D; d += 32) {
        float v = a[(size_t)r * D + d];
        s = fmaf(v, v, s);
    }
    #pragma unroll
    for (int o = 16; o; o >>= 1) s += __shfl_xor_sync(0xFFFFFFFFu, s, o);
    if (lane == 0) out[r] = s;
}

__global__ void best_reset(unsigned long long* __restrict__ best, int n)
{
    int i = blockIdx.x * blockDim.x + threadIdx.x;
    if (i < n) best[i] = 0xFFFFFFFFFFFFFFFFull;
}

__global__ void labels_scatter(const unsigned long long* __restrict__ best,
                               float* __restrict__ labels)
{
    const int row = blockIdx.x, tid = threadIdx.x;
    const int win = (int)(unsigned int)(best[row] & 0xFFFFFFFFull);
    float4* lp = reinterpret_cast<float4*>(labels + (size_t)row * K_CENT);
    #pragma unroll
    for (int k4 = tid; k4 < K_CENT / 4; k4 += 256) {
        int k = k4 * 4;
        float4 v;
        v.x = (k == win) ? 1.0f : 0.0f;
        v.y = (k + 1 == win) ? 1.0f : 0.0f;
        v.z = (k + 2 == win) ? 1.0f : 0.0f;
        v.w = (k + 3 == win) ? 1.0f : 0.0f;
        lp[k4] = v;
    }
}

// ---------------- host launcher ----------------
extern "C" void kernel_launch(void* const* d_in, const int* in_sizes, int n_in,
                              void* d_out, int out_size)
{
    (void)in_sizes; (void)n_in; (void)out_size;

    static cudaStream_t sB = nullptr;
    static cudaEvent_t evFork = nullptr, evPrep = nullptr, evEmb = nullptr, evJoin = nullptr;
    if (!sB) {
        cudaStreamCreateWithFlags(&sB, cudaStreamNonBlocking);
        cudaEventCreateWithFlags(&evFork, cudaEventDisableTiming);
        cudaEventCreateWithFlags(&evPrep, cudaEventDisableTiming);
        cudaEventCreateWithFlags(&evEmb,  cudaEventDisableTiming);
        cudaEventCreateWithFlags(&evJoin, cudaEventDisableTiming);
    }

    cudaFuncSetAttribute(gemm_fp16e, cudaFuncAttributeMaxDynamicSharedMemorySize, FP16E_SMEM);
    cudaFuncSetAttribute(gemm_fp16s, cudaFuncAttributeMaxDynamicSharedMemorySize, FP16S_SMEM);

    const float* x = (const float*)d_in[0];
    const float* W[8]  = {(const float*)d_in[1],  (const float*)d_in[3],
                          (const float*)d_in[5],  (const float*)d_in[7],
                          (const float*)d_in[9],  (const float*)d_in[11],
                          (const float*)d_in[13], (const float*)d_in[15]};
    const float* bv[8] = {(const float*)d_in[2],  (const float*)d_in[4],
                          (const float*)d_in[6],  (const float*)d_in[8],
                          (const float*)d_in[10], (const float*)d_in[12],
                          (const float*)d_in[14], (const float*)d_in[16]};
    const float* centers = (const float*)d_in[17];

    float* out    = (float*)d_out;
    float* recon  = out;
    float* emb    = out + (size_t)B_ROWS * D_IN;
    float* labels = emb + (size_t)B_ROWS * D_EMB;

    __half *xh, *xl, *h0h, *h0l, *h1h, *h1l, *dc0, *dc1, *eh, *el, *weh, *wel, *wd, *ch, *cl;
    float *c2, *e2v;
    unsigned long long* best;
    cudaGetSymbolAddress((void**)&xh, g_xh);   cudaGetSymbolAddress((void**)&xl, g_xl);
    cudaGetSymbolAddress((void**)&h0h, g_h0h); cudaGetSymbolAddress((void**)&h0l, g_h0l);
    cudaGetSymbolAddress((void**)&h1h, g_h1h); cudaGetSymbolAddress((void**)&h1l, g_h1l);
    cudaGetSymbolAddress((void**)&dc0, g_dc0); cudaGetSymbolAddress((void**)&dc1, g_dc1);
    cudaGetSymbolAddress((void**)&eh, g_eh);   cudaGetSymbolAddress((void**)&el, g_el);
    cudaGetSymbolAddress((void**)&weh, g_weh); cudaGetSymbolAddress((void**)&wel, g_wel);
    cudaGetSymbolAddress((void**)&wd, g_wd);
    cudaGetSymbolAddress((void**)&ch, g_ch);   cudaGetSymbolAddress((void**)&cl, g_cl);
    cudaGetSymbolAddress((void**)&c2, g_c2);   cudaGetSymbolAddress((void**)&e2v, g_e2);
    cudaGetSymbolAddress((void**)&best, g_best);

    const int fi[8] = {1024, 2048, 1024, 512, 256, 512, 1024, 2048};
    const int fo[8] = {2048, 1024, 512, 256, 512, 1024, 2048, 1024};
    size_t off[8], acc = 0, accd = 0;
    for (int i = 0; i < 4; i++) { off[i] = acc;  acc  += (size_t)fi[i] * fo[i]; }
    for (int i = 4; i < 8; i++) { off[i] = accd; accd += (size_t)fi[i] * fo[i]; }

    // ---- fork side stream: everything not needed before GEMM1 ----
    cudaEventRecord(evFork, 0);
    cudaStreamWaitEvent(sB, evFork, 0);
    rowsq_kernel<<<K_CENT / 8, 256, 0, sB>>>(centers, c2, D_EMB);
    vec_split_fp16<<<(K_CENT * D_EMB / 2 + 255) / 256, 256, 0, sB>>>(
        centers, ch, cl, K_CENT * D_EMB / 2);
    best_reset<<<(B_ROWS + 255) / 256, 256, 0, sB>>>(best, B_ROWS);
    for (int i = 1; i < 4; i++) {
        dim3 g(fo[i] / 32, fi[i] / 32), b(32, 8);
        wt_split_fp16<<<g, b, 0, sB>>>(W[i], weh + off[i], wel + off[i], fi[i], fo[i]);
    }
    for (int i = 4; i < 8; i++) {
        dim3 g(fo[i] / 32, fi[i] / 32), b(32, 8);
        wt_single_fp16<<<g, b, 0, sB>>>(W[i], wd + off[i], fi[i], fo[i]);
    }
    cudaEventRecord(evPrep, sB);

    // ---- main stream: minimal prep + encoder ----
    vec_split_fp16<<<(B_ROWS * D_IN / 2 + 255) / 256, 256>>>(x, xh, xl, B_ROWS * D_IN / 2);
    {
        dim3 g(fo[0] / 32, fi[0] / 32), b(32, 8);
        wt_split_fp16<<<g, b>>>(W[0], weh + off[0], wel + off[0], fi[0], fo[0]);
    }
    {
        dim3 g0(2048 / 64, B_ROWS / 128);
        gemm_fp16e<<<g0, 256, FP16E_SMEM>>>(xh, xl, weh + off[0], wel + off[0], bv[0],
                                            nullptr, h0h, h0l, nullptr, nullptr, nullptr,
                                            B_ROWS, 2048, 1024, 1);
    }
    cudaStreamWaitEvent(0, evPrep, 0);
    {
        dim3 g1(1024 / 64, B_ROWS / 128);
        gemm_fp16e<<<g1, 256, FP16E_SMEM>>>(h0h, h0l, weh + off[1], wel + off[1], bv[1],
                                            nullptr, h1h, h1l, nullptr, nullptr, nullptr,
                                            B_ROWS, 1024, 2048, 1);
        dim3 g2(512 / 64, B_ROWS / 128);
        gemm_fp16e<<<g2, 256, FP16E_SMEM>>>(h1h, h1l, weh + off[2], wel + off[2], bv[2],
                                            nullptr, h0h, h0l, nullptr, nullptr, nullptr,
                                            B_ROWS, 512, 1024, 1);
        dim3 g3(256 / 64, B_ROWS / 128);
        gemm_fp16e<<<g3, 256, FP16E_SMEM>>>(h0h, h0l, weh + off[3], wel + off[3], bv[3],
                                            emb, eh, el, nullptr, nullptr, nullptr,
                                            B_ROWS, 256, 512, 0);
    }
    cudaEventRecord(evEmb, 0);

    // ---- side stream: decoder chain ----
    cudaStreamWaitEvent(sB, evEmb, 0);
    {
        dim3 g0(512 / 64, B_ROWS / 128);
        gemm_fp16s<<<g0, 256, FP16S_SMEM, sB>>>(eh, wd + off[4], bv[4],
                                                nullptr, dc0, B_ROWS, 512, 256, 1);
        dim3 g1(1024 / 64, B_ROWS / 128);
        gemm_fp16s<<<g1, 256, FP16S_SMEM, sB>>>(dc0, wd + off[5], bv[5],
                                                nullptr, dc1, B_ROWS, 1024, 512, 1);
        dim3 g2(2048 / 64, B_ROWS / 128);
        gemm_fp16s<<<g2, 256, FP16S_SMEM, sB>>>(dc1, wd + off[6], bv[6],
                                                nullptr, dc0, B_ROWS, 2048, 1024, 1);
        dim3 g3(1024 / 64, B_ROWS / 128);
        gemm_fp16s<<<g3, 256, FP16S_SMEM, sB>>>(dc0, wd + off[7], bv[7],
                                                recon, nullptr, B_ROWS, 1024, 2048, 0);
    }
    cudaEventRecord(evJoin, sB);

    // ---- main stream: fused clustering ----
    rowsq_kernel<<<B_ROWS / 8, 256>>>(emb, e2v, D_EMB);
    {
        dim3 g(K_CENT / 64, B_ROWS / 128);
        gemm_fp16e<<<g, 256, FP16E_SMEM>>>(eh, el, ch, cl, nullptr,
                                           nullptr, nullptr, nullptr, e2v, c2, best,
                                           B_ROWS, K_CENT, D_EMB, 0);
    }
    labels_scatter<<<B_ROWS, 256>>>(best, labels);

    // ---- join decoder ----
    cudaStreamWaitEvent(0, evJoin, 0);
}